// round 3
// baseline (speedup 1.0000x reference)
#include <cuda_runtime.h>
#include <math.h>

#define S     768
#define CS    384
#define CP    128
#define EMB   16
#define PQN   4
#define PVN   8
#define NH    12
#define NPROJ 1152          // 3*H*E + 2*H*PQ*3 + H*PV*3 = 576+288+288
#define FEAT  2112          // H*(E + CP + PV*3 + PV)
#define UC    48            // padded combined [v(16) | lvp(24) | zero-pad(8)]

// ---------------- scratch (device globals; no allocations allowed) -------
__device__ float g_P[S * NPROJ];        // packed projections [s][n]
__device__ float g_q[NH * S * EMB];     // [h][s][e]
__device__ float g_kT[NH * EMB * S];    // [h][e][s]
__device__ float g_lqp[NH * S * 12];    // [h][s][p*3+d]
__device__ float g_lkpT[NH * 12 * S];   // [h][p*3+d][s]
__device__ float g_U[NH * S * UC];      // [h][s][48]: v | lvp | 0
__device__ float g_wpair[NH * S * S];   // [h][i][j]
__device__ float g_a[NH * S * S];       // softmax output
__device__ float g_asumT[S * NH];       // [k][h]
__device__ float g_oc[NH * S * UC];     // [h][i][48]: o_single | o_local
__device__ float g_feat[S * FEAT];      // concatenated attention features

// ---------------- K1: packed projection GEMM  P = single @ Wall^T --------
// M=768, N=1152, K=384. 64x64 tiles, 256 thr, 4x4 register tile.
__global__ void k_proj(const float* __restrict__ single,
                       const float* __restrict__ Wq, const float* __restrict__ Wk,
                       const float* __restrict__ Wv, const float* __restrict__ Wqp,
                       const float* __restrict__ Wkp, const float* __restrict__ Wvp) {
    __shared__ float As[32 * 68];
    __shared__ float Bs[32 * 68];
    const int n0 = blockIdx.x * 64, m0 = blockIdx.y * 64;
    const int t  = threadIdx.x;
    const int i0 = (t & 15) * 4, j0 = (t >> 4) * 4;
    float acc[4][4] = {};

    for (int kt = 0; kt < CS; kt += 32) {
#pragma unroll
        for (int r = 0; r < 8; r++) {                  // stage A (64m x 32k)
            int idx = t + 256 * r;
            int i = idx >> 5, k = idx & 31;
            As[k * 68 + i] = single[(m0 + i) * CS + kt + k];
        }
#pragma unroll
        for (int r = 0; r < 8; r++) {                  // stage B (64n x 32k)
            int idx = t + 256 * r;
            int j = idx >> 5, k = idx & 31;
            int n = n0 + j;
            const float* row;
            if (n < 192)      row = Wq  + n * CS;
            else if (n < 384) row = Wk  + (n - 192) * CS;
            else if (n < 576) row = Wv  + (n - 384) * CS;
            else if (n < 720) row = Wqp + (n - 576) * CS;
            else if (n < 864) row = Wkp + (n - 720) * CS;
            else              row = Wvp + (n - 864) * CS;
            Bs[k * 68 + j] = row[kt + k];
        }
        __syncthreads();
#pragma unroll
        for (int k = 0; k < 32; k++) {
            float4 a4 = *(const float4*)&As[k * 68 + i0];
            float4 b4 = *(const float4*)&Bs[k * 68 + j0];
            float av[4] = {a4.x, a4.y, a4.z, a4.w};
            float bv[4] = {b4.x, b4.y, b4.z, b4.w};
#pragma unroll
            for (int ii = 0; ii < 4; ii++)
#pragma unroll
                for (int jj = 0; jj < 4; jj++) acc[ii][jj] += av[ii] * bv[jj];
        }
        __syncthreads();
    }
#pragma unroll
    for (int ii = 0; ii < 4; ii++)
#pragma unroll
        for (int jj = 0; jj < 4; jj++)
            g_P[(m0 + i0 + ii) * NPROJ + n0 + j0 + jj] = acc[ii][jj];
}

// ---------------- K1b: frame apply + scatter to compute layouts ----------
__global__ void k_frames(const float* __restrict__ rot, const float* __restrict__ trans) {
    int idx = blockIdx.x * blockDim.x + threadIdx.x;
    if (idx >= NH * S) return;
    int h = idx / S, s = idx % S;
    float R[3][3], tv[3];
#pragma unroll
    for (int a = 0; a < 3; a++) {
        tv[a] = trans[s * 3 + a];
#pragma unroll
        for (int b = 0; b < 3; b++) R[a][b] = rot[s * 9 + a * 3 + b];
    }
    const float* Ps = g_P + (size_t)s * NPROJ;
#pragma unroll
    for (int e = 0; e < EMB; e++) {
        g_q[(h * S + s) * EMB + e]       = Ps[h * EMB + e];
        g_kT[(h * EMB + e) * S + s]      = Ps[192 + h * EMB + e];
        g_U[(size_t)(h * S + s) * UC + e] = Ps[384 + h * EMB + e];
    }
#pragma unroll
    for (int p = 0; p < PQN; p++) {                    // query points
        float x0 = Ps[576 + h * 12 + p * 3 + 0];
        float x1 = Ps[576 + h * 12 + p * 3 + 1];
        float x2 = Ps[576 + h * 12 + p * 3 + 2];
#pragma unroll
        for (int a = 0; a < 3; a++)
            g_lqp[(h * S + s) * 12 + p * 3 + a] = R[a][0] * x0 + R[a][1] * x1 + R[a][2] * x2 + tv[a];
    }
#pragma unroll
    for (int p = 0; p < PQN; p++) {                    // key points (transposed out)
        float x0 = Ps[720 + h * 12 + p * 3 + 0];
        float x1 = Ps[720 + h * 12 + p * 3 + 1];
        float x2 = Ps[720 + h * 12 + p * 3 + 2];
#pragma unroll
        for (int a = 0; a < 3; a++)
            g_lkpT[(h * 12 + p * 3 + a) * S + s] = R[a][0] * x0 + R[a][1] * x1 + R[a][2] * x2 + tv[a];
    }
#pragma unroll
    for (int p = 0; p < PVN; p++) {                    // value points
        float x0 = Ps[864 + h * 24 + p * 3 + 0];
        float x1 = Ps[864 + h * 24 + p * 3 + 1];
        float x2 = Ps[864 + h * 24 + p * 3 + 2];
#pragma unroll
        for (int a = 0; a < 3; a++)
            g_U[(size_t)(h * S + s) * UC + 16 + p * 3 + a] =
                R[a][0] * x0 + R[a][1] * x1 + R[a][2] * x2 + tv[a];
    }
#pragma unroll
    for (int c = 40; c < UC; c++) g_U[(size_t)(h * S + s) * UC + c] = 0.0f;
}

// ---------------- K2: w_pair[h,i,j] = sum_c Wb[h,c] * pair[i,j,c] --------
// block: (i fixed, 256-j tile). SMEM pair tile XOR-swizzled float4.
__global__ void k_wpair(const float* __restrict__ pair, const float* __restrict__ Wb) {
    extern __shared__ float sm[];
    float4* sp  = (float4*)sm;               // [256 j][32 q] swizzled
    float*  swb = sm + 256 * 128;            // [12][128]
    const int i  = blockIdx.y;
    const int j0 = blockIdx.x * 256;
    const int t  = threadIdx.x;

    for (int x = t; x < NH * CP; x += 256) swb[x] = Wb[x];
    const float4* gp = (const float4*)(pair + ((size_t)i * S + j0) * CP);
#pragma unroll
    for (int r = 0; r < 32; r++) {
        int idx = t + 256 * r;
        int j = idx >> 5, q = idx & 31;
        sp[j * 32 + (q ^ (j & 31))] = gp[j * 32 + q];
    }
    __syncthreads();

    const int jA = t & 127, jB = jA + 128;
    const int h0 = (t >> 7) * 6;
    float accA[6] = {}, accB[6] = {};
#pragma unroll
    for (int q = 0; q < 32; q++) {
        float4 pA = sp[jA * 32 + (q ^ (jA & 31))];
        float4 pB = sp[jB * 32 + (q ^ (jA & 31))];
#pragma unroll
        for (int hh = 0; hh < 6; hh++) {
            float4 w = *(const float4*)&swb[(h0 + hh) * 128 + q * 4];
            accA[hh] += pA.x * w.x + pA.y * w.y + pA.z * w.z + pA.w * w.w;
            accB[hh] += pB.x * w.x + pB.y * w.y + pB.z * w.z + pB.w * w.w;
        }
    }
#pragma unroll
    for (int hh = 0; hh < 6; hh++) {
        int h = h0 + hh;
        g_wpair[((size_t)h * S + i) * S + j0 + jA] = accA[hh];
        g_wpair[((size_t)h * S + i) * S + j0 + jB] = accB[hh];
    }
}

// ---------------- K3: logits (single + pair + frame) and softmax ---------
// block: (h, 16 query rows). 512 thr, one warp per row. kT/lkpT in SMEM.
__global__ void k_soft(const float* __restrict__ gamma) {
    extern __shared__ float sm[];
    float* ks  = sm;                 // [16 e][768 j]
    float* lks = sm + EMB * S;       // [12 d][768 j]
    const int h  = blockIdx.y;
    const int i0 = blockIdx.x * 16;
    const int t  = threadIdx.x;

    for (int x = t; x < EMB * S; x += 512) ks[x]  = g_kT[h * EMB * S + x];
    for (int x = t; x < 12 * S;  x += 512) lks[x] = g_lkpT[h * 12 * S + x];
    __syncthreads();

    const int w = t >> 5, lane = t & 31;
    const int i = i0 + w;
    float qv[EMB], pv[12];
#pragma unroll
    for (int e = 0; e < EMB; e++) qv[e] = g_q[(h * S + i) * EMB + e];
#pragma unroll
    for (int d = 0; d < 12; d++)  pv[d] = g_lqp[(h * S + i) * 12 + d];
    float g  = gamma[h];
    float cf = -0.11785113f * logf(1.0f + expf(g));   // scale_frame * softplus(gamma)
    const float* wp = g_wpair + ((size_t)h * S + i) * S;

    float l[24];
    float m = -1e30f;
#pragma unroll
    for (int jj = 0; jj < 24; jj++) {
        int j = jj * 32 + lane;
        float dot = 0.0f;
#pragma unroll
        for (int e = 0; e < EMB; e++) dot += qv[e] * ks[e * S + j];
        float dd = 0.0f;
#pragma unroll
        for (int d = 0; d < 12; d++) { float df = pv[d] - lks[d * S + j]; dd += df * df; }
        float lg = 0.25f * dot + wp[j] + cf * dd;     // 1/sqrt(16) = 0.25
        l[jj] = lg;
        m = fmaxf(m, lg);
    }
#pragma unroll
    for (int o = 16; o > 0; o >>= 1) m = fmaxf(m, __shfl_xor_sync(0xffffffffu, m, o));
    float sum = 0.0f;
#pragma unroll
    for (int jj = 0; jj < 24; jj++) { float e = __expf(l[jj] - m); l[jj] = e; sum += e; }
#pragma unroll
    for (int o = 16; o > 0; o >>= 1) sum += __shfl_xor_sync(0xffffffffu, sum, o);
    float inv = 1.0f / sum;
    float* ap = g_a + ((size_t)h * S + i) * S;
#pragma unroll
    for (int jj = 0; jj < 24; jj++) ap[jj * 32 + lane] = l[jj] * inv;
}

// ---------------- K4: a_sum[k,h] = sum_i a[h,i,k] -------------------------
__global__ void k_asum() {
    int j = blockIdx.x * 256 + threadIdx.x;
    int h = blockIdx.y;
    float acc = 0.0f;
    const float* ap = g_a + (size_t)h * S * S + j;
    for (int i = 0; i < S; i++) acc += ap[(size_t)i * S];
    g_asumT[j * NH + h] = acc;
}

// ---------------- K5: o_combined[h,i,:48] = a[h,i,:] @ U[h,:, :48] -------
// block: (h, 32-i tile). 128 thr, thread owns (i, 12 cols).
__global__ void k_av() {
    __shared__ float sa[32 * 128];
    __shared__ float su[128 * UC];
    const int h  = blockIdx.y;
    const int i0 = blockIdx.x * 32;
    const int t  = threadIdx.x;          // 128
    const int i  = t & 31, cg = t >> 5;  // cg 0..3
    const int c0 = cg * 12;
    float acc[12] = {};

    for (int jt = 0; jt < S; jt += 128) {
#pragma unroll
        for (int r = 0; r < 32; r++) {                 // stage a: 32 x 128, swizzled
            int idx = t + 128 * r;
            int ii = idx >> 7, j = idx & 127;
            sa[ii * 128 + ((j + ii) & 127)] = g_a[((size_t)h * S + i0 + ii) * S + jt + j];
        }
#pragma unroll
        for (int r = 0; r < 48; r++) {                 // stage U: 128 x 48
            int idx = t + 128 * r;
            su[idx] = g_U[((size_t)h * S + jt) * UC + idx];
        }
        __syncthreads();
#pragma unroll 4
        for (int j = 0; j < 128; j++) {
            float av = sa[i * 128 + ((j + i) & 127)];
            float4 u0 = *(const float4*)&su[j * UC + c0];
            float4 u1 = *(const float4*)&su[j * UC + c0 + 4];
            float4 u2 = *(const float4*)&su[j * UC + c0 + 8];
            acc[0]  += av * u0.x; acc[1]  += av * u0.y; acc[2]  += av * u0.z; acc[3]  += av * u0.w;
            acc[4]  += av * u1.x; acc[5]  += av * u1.y; acc[6]  += av * u1.z; acc[7]  += av * u1.w;
            acc[8]  += av * u2.x; acc[9]  += av * u2.y; acc[10] += av * u2.z; acc[11] += av * u2.w;
        }
        __syncthreads();
    }
    float* op = g_oc + ((size_t)h * S + i0 + i) * UC + c0;
#pragma unroll
    for (int w = 0; w < 12; w++) op[w] = acc[w];
}

// ---------------- K6: inverse frame + scatter into feature buffer --------
__global__ void k_scatter(const float* __restrict__ rot, const float* __restrict__ trans) {
    int idx = blockIdx.x * blockDim.x + threadIdx.x;
    if (idx >= NH * S) return;
    int h = idx / S, s = idx % S;
    const float* oc = g_oc + (size_t)(h * S + s) * UC;
    float* f = g_feat + (size_t)s * FEAT;
#pragma unroll
    for (int e = 0; e < EMB; e++) f[h * EMB + e] = oc[e];   // o_single block

    float R[3][3], tv[3];
#pragma unroll
    for (int a = 0; a < 3; a++) {
        tv[a] = trans[s * 3 + a];
#pragma unroll
        for (int b = 0; b < 3; b++) R[a][b] = rot[s * 9 + a * 3 + b];
    }
#pragma unroll
    for (int p = 0; p < PVN; p++) {
        float x0 = oc[16 + p * 3 + 0] - tv[0];
        float x1 = oc[16 + p * 3 + 1] - tv[1];
        float x2 = oc[16 + p * 3 + 2] - tv[2];
        float og[3];
#pragma unroll
        for (int a = 0; a < 3; a++) og[a] = R[0][a] * x0 + R[1][a] * x1 + R[2][a] * x2;  // R^T(x)
#pragma unroll
        for (int a = 0; a < 3; a++) f[1728 + p * 36 + h * 3 + a] = og[a];
        f[2016 + p * 12 + h] = sqrtf(og[0] * og[0] + og[1] * og[1] + og[2] * og[2]);
    }
}

// ---------------- K7: o_pair[i,h,c] = sum_k a_sum[k,h] * pair[i,k,c] -----
__global__ void k_opair(const float* __restrict__ pair) {
    __shared__ float sas[S * NH];                       // 36 KB
    const int i = blockIdx.x;
    const int t = threadIdx.x;                           // 128 = CP
    for (int x = t; x < S * NH; x += 128) sas[x] = g_asumT[x];
    __syncthreads();

    float acc[12] = {};
    const float* pp = pair + (size_t)i * S * CP + t;
#pragma unroll 4
    for (int k = 0; k < S; k++) {
        float p = __ldg(pp + (size_t)k * CP);
        float4 a0 = *(const float4*)&sas[k * 12];
        float4 a1 = *(const float4*)&sas[k * 12 + 4];
        float4 a2 = *(const float4*)&sas[k * 12 + 8];
        acc[0]  += p * a0.x; acc[1]  += p * a0.y; acc[2]  += p * a0.z; acc[3]  += p * a0.w;
        acc[4]  += p * a1.x; acc[5]  += p * a1.y; acc[6]  += p * a1.z; acc[7]  += p * a1.w;
        acc[8]  += p * a2.x; acc[9]  += p * a2.y; acc[10] += p * a2.z; acc[11] += p * a2.w;
    }
    float* f = g_feat + (size_t)i * FEAT + 192 + t;
#pragma unroll
    for (int h = 0; h < NH; h++) f[h * CP] = acc[h];
}

// ---------------- K8: out = feat @ Wo^T + bo ------------------------------
// M=768, N=384, K=2112. 32x64 tiles, 256 thr, 2x4 register tile.
__global__ void k_out(const float* __restrict__ Wo, const float* __restrict__ bo,
                      float* __restrict__ out) {
    __shared__ float As[32 * 36];
    __shared__ float Bs[32 * 68];
    const int m0 = blockIdx.y * 32, n0 = blockIdx.x * 64;
    const int t  = threadIdx.x;
    const int i0 = (t & 15) * 2, j0 = (t >> 4) * 4;
    float acc[2][4] = {};

    for (int kt = 0; kt < FEAT; kt += 32) {
#pragma unroll
        for (int r = 0; r < 4; r++) {                  // stage A (32m x 32k)
            int idx = t + 256 * r;
            int i = idx >> 5, k = idx & 31;
            As[k * 36 + i] = g_feat[(size_t)(m0 + i) * FEAT + kt + k];
        }
#pragma unroll
        for (int r = 0; r < 8; r++) {                  // stage B (64n x 32k)
            int idx = t + 256 * r;
            int j = idx >> 5, k = idx & 31;
            Bs[k * 68 + j] = Wo[(size_t)(n0 + j) * FEAT + kt + k];
        }
        __syncthreads();
#pragma unroll
        for (int k = 0; k < 32; k++) {
            float2 a2 = *(const float2*)&As[k * 36 + i0];
            float4 b4 = *(const float4*)&Bs[k * 68 + j0];
            acc[0][0] += a2.x * b4.x; acc[0][1] += a2.x * b4.y;
            acc[0][2] += a2.x * b4.z; acc[0][3] += a2.x * b4.w;
            acc[1][0] += a2.y * b4.x; acc[1][1] += a2.y * b4.y;
            acc[1][2] += a2.y * b4.z; acc[1][3] += a2.y * b4.w;
        }
        __syncthreads();
    }
#pragma unroll
    for (int ii = 0; ii < 2; ii++)
#pragma unroll
        for (int jj = 0; jj < 4; jj++)
            out[(m0 + i0 + ii) * CS + n0 + j0 + jj] = acc[ii][jj] + bo[n0 + j0 + jj];
}

// --------------------------------------------------------------------------
extern "C" void kernel_launch(void* const* d_in, const int* in_sizes, int n_in,
                              void* d_out, int out_size) {
    const float* single = (const float*)d_in[0];
    const float* pair   = (const float*)d_in[1];
    const float* rot    = (const float*)d_in[2];
    const float* trans  = (const float*)d_in[3];
    const float* Wq     = (const float*)d_in[4];
    const float* Wk     = (const float*)d_in[5];
    const float* Wv     = (const float*)d_in[6];
    const float* Wqp    = (const float*)d_in[7];
    const float* Wkp    = (const float*)d_in[8];
    const float* Wvp    = (const float*)d_in[9];
    const float* Wb     = (const float*)d_in[10];
    const float* Wo     = (const float*)d_in[11];
    const float* bo     = (const float*)d_in[12];
    const float* gamma  = (const float*)d_in[13];
    float* out = (float*)d_out;

    const int SMEM_WPAIR = 256 * 128 * 4 + NH * CP * 4;   // 137216 B
    const int SMEM_SOFT  = (EMB + 12) * S * 4;            // 86016 B
    cudaFuncSetAttribute(k_wpair, cudaFuncAttributeMaxDynamicSharedMemorySize, SMEM_WPAIR);
    cudaFuncSetAttribute(k_soft,  cudaFuncAttributeMaxDynamicSharedMemorySize, SMEM_SOFT);

    k_proj   <<<dim3(NPROJ / 64, S / 64), 256>>>(single, Wq, Wk, Wv, Wqp, Wkp, Wvp);
    k_frames <<<(NH * S + 255) / 256, 256>>>(rot, trans);
    k_wpair  <<<dim3(S / 256, S), 256, SMEM_WPAIR>>>(pair, Wb);
    k_soft   <<<dim3(S / 16, NH), 512, SMEM_SOFT>>>(gamma);
    k_asum   <<<dim3(S / 256, NH), 256>>>();
    k_av     <<<dim3(S / 32, NH), 128>>>();
    k_scatter<<<(NH * S + 255) / 256, 256>>>(rot, trans);
    k_opair  <<<S, 128>>>(pair);
    k_out    <<<dim3(CS / 64, S / 32), 256>>>(Wo, bo, out);
}

// round 4
// speedup vs baseline: 1.1144x; 1.1144x over previous
#include <cuda_runtime.h>
#include <math.h>

#define S     768
#define CS    384
#define CP    128
#define EMB   16
#define NH    12
#define NPROJ 1152          // 3*H*E + 2*H*PQ*3 + H*PV*3
#define FEAT  2112          // H*(E + CP + PV*3 + PV)
#define UC    48            // padded combined [v(16) | lvp(24) | zero-pad(8)]
#define KD    29            // augmented K' dims: k(16) + lkp(12) + cf*|lkp|^2(1)

typedef unsigned long long u64;

// ---- packed fp32x2 FMA (FFMA2 — PTX-only on sm_103a) --------------------
__device__ __forceinline__ u64 pk(float x, float y) {
    u64 r; asm("mov.b64 %0, {%1,%2};" : "=l"(r) : "f"(x), "f"(y)); return r;
}
__device__ __forceinline__ float2 upk(u64 v) {
    float2 r; asm("mov.b64 {%0,%1}, %2;" : "=f"(r.x), "=f"(r.y) : "l"(v)); return r;
}
__device__ __forceinline__ void fma2(u64& d, u64 a, u64 b) {
    asm("fma.rn.f32x2 %0, %1, %2, %0;" : "+l"(d) : "l"(a), "l"(b));
}

// ---------------- scratch (device globals) --------------------------------
__device__ float g_P[S * NPROJ];          // packed projections [s][n]
__device__ float g_qp2[NH * S * 32];      // Q' [h][s][32]: 0.25q | -2cf*lqp | 1 | pad
__device__ float g_kp2[NH * KD * S];      // K' [h][e'][s]: k | lkp | cf*|lkp|^2
__device__ float g_U[NH * S * UC];        // [h][s][48]: v | lvp | 0
__device__ float g_wpair[NH * S * S];
__device__ float g_a[NH * S * S];
__device__ float g_asp[12 * S * NH];      // partial column sums [z][j][h]
__device__ float g_asumT[S * NH];         // [k][h]
__device__ float g_oc[NH * S * UC];       // [h][i][48]: o_single | o_local
__device__ float g_feat[S * FEAT];

// ---------------- K1: packed projection GEMM P = single @ Wall^T ----------
__global__ void k_proj(const float* __restrict__ single,
                       const float* __restrict__ Wq, const float* __restrict__ Wk,
                       const float* __restrict__ Wv, const float* __restrict__ Wqp,
                       const float* __restrict__ Wkp, const float* __restrict__ Wvp) {
    __shared__ float As[32 * 68];
    __shared__ float Bs[32 * 68];
    const int n0 = blockIdx.x * 64, m0 = blockIdx.y * 64;
    const int t  = threadIdx.x;
    const int i0 = (t & 15) * 4, j0 = (t >> 4) * 4;
    u64 acc[4][2] = {};

    for (int kt = 0; kt < CS; kt += 32) {
#pragma unroll
        for (int r = 0; r < 8; r++) {
            int idx = t + 256 * r;
            int i = idx >> 5, k = idx & 31;
            As[k * 68 + i] = single[(m0 + i) * CS + kt + k];
        }
#pragma unroll
        for (int r = 0; r < 8; r++) {
            int idx = t + 256 * r;
            int j = idx >> 5, k = idx & 31;
            int n = n0 + j;
            const float* row;
            if (n < 192)      row = Wq  + n * CS;
            else if (n < 384) row = Wk  + (n - 192) * CS;
            else if (n < 576) row = Wv  + (n - 384) * CS;
            else if (n < 720) row = Wqp + (n - 576) * CS;
            else if (n < 864) row = Wkp + (n - 720) * CS;
            else              row = Wvp + (n - 864) * CS;
            Bs[k * 68 + j] = row[kt + k];
        }
        __syncthreads();
#pragma unroll
        for (int k = 0; k < 32; k++) {
            float4 a4 = *(const float4*)&As[k * 68 + i0];
            float4 b4 = *(const float4*)&Bs[k * 68 + j0];
            u64 bxy = pk(b4.x, b4.y), bzw = pk(b4.z, b4.w);
            float av[4] = {a4.x, a4.y, a4.z, a4.w};
#pragma unroll
            for (int ii = 0; ii < 4; ii++) {
                u64 aa = pk(av[ii], av[ii]);
                fma2(acc[ii][0], aa, bxy);
                fma2(acc[ii][1], aa, bzw);
            }
        }
        __syncthreads();
    }
#pragma unroll
    for (int ii = 0; ii < 4; ii++) {
        float2 lo = upk(acc[ii][0]), hi = upk(acc[ii][1]);
        float* o = &g_P[(m0 + i0 + ii) * NPROJ + n0 + j0];
        o[0] = lo.x; o[1] = lo.y; o[2] = hi.x; o[3] = hi.y;
    }
}

// ---------------- K1b: frame apply + augmented Q'/K' build ----------------
__global__ void k_frames(const float* __restrict__ rot, const float* __restrict__ trans,
                         const float* __restrict__ gamma) {
    int idx = blockIdx.x * blockDim.x + threadIdx.x;
    if (idx >= NH * S) return;
    int h = idx / S, s = idx % S;

    float g  = gamma[h];
    float sp = (g > 20.f) ? g : log1pf(expf(g));
    float cf = -0.11785113f * sp;          // -softplus(gamma)/sqrt(72)

    float R[3][3], tv[3];
#pragma unroll
    for (int a = 0; a < 3; a++) {
        tv[a] = trans[s * 3 + a];
#pragma unroll
        for (int b = 0; b < 3; b++) R[a][b] = rot[s * 9 + a * 3 + b];
    }
    const float* Ps = g_P + (size_t)s * NPROJ;
    float* qp2 = g_qp2 + (size_t)(h * S + s) * 32;

#pragma unroll
    for (int e = 0; e < EMB; e++) {
        qp2[e] = 0.25f * Ps[h * EMB + e];
        g_kp2[(h * KD + e) * S + s]        = Ps[192 + h * EMB + e];
        g_U[(size_t)(h * S + s) * UC + e]  = Ps[384 + h * EMB + e];
    }
    float m2cf = -2.0f * cf;
#pragma unroll
    for (int p = 0; p < 4; p++) {          // query points (scaled into Q')
        float x0 = Ps[576 + h * 12 + p * 3 + 0];
        float x1 = Ps[576 + h * 12 + p * 3 + 1];
        float x2 = Ps[576 + h * 12 + p * 3 + 2];
#pragma unroll
        for (int a = 0; a < 3; a++) {
            float l = R[a][0] * x0 + R[a][1] * x1 + R[a][2] * x2 + tv[a];
            qp2[16 + p * 3 + a] = m2cf * l;
        }
    }
    qp2[28] = 1.0f; qp2[29] = 0.0f; qp2[30] = 0.0f; qp2[31] = 0.0f;

    float nk = 0.0f;
#pragma unroll
    for (int p = 0; p < 4; p++) {          // key points (+ norm row)
        float x0 = Ps[720 + h * 12 + p * 3 + 0];
        float x1 = Ps[720 + h * 12 + p * 3 + 1];
        float x2 = Ps[720 + h * 12 + p * 3 + 2];
#pragma unroll
        for (int a = 0; a < 3; a++) {
            float l = R[a][0] * x0 + R[a][1] * x1 + R[a][2] * x2 + tv[a];
            g_kp2[(h * KD + 16 + p * 3 + a) * S + s] = l;
            nk += l * l;
        }
    }
    g_kp2[(h * KD + 28) * S + s] = cf * nk;

#pragma unroll
    for (int p = 0; p < 8; p++) {          // value points
        float x0 = Ps[864 + h * 24 + p * 3 + 0];
        float x1 = Ps[864 + h * 24 + p * 3 + 1];
        float x2 = Ps[864 + h * 24 + p * 3 + 2];
#pragma unroll
        for (int a = 0; a < 3; a++)
            g_U[(size_t)(h * S + s) * UC + 16 + p * 3 + a] =
                R[a][0] * x0 + R[a][1] * x1 + R[a][2] * x2 + tv[a];
    }
#pragma unroll
    for (int c = 40; c < UC; c++) g_U[(size_t)(h * S + s) * UC + c] = 0.0f;
}

// ---------------- K2: w_pair[h,i,j] = sum_c Wb[h,c]*pair[i,j,c] ------------
// grid (12 j-tiles, 768 i), 256 thr, 64-j tile (39KB smem -> 5 blocks/SM).
// lane = jq*4+hq: warp covers 8 j x 12 heads; pair-tile LDS.128 is 1-phase.
__global__ void __launch_bounds__(256) k_wpair(const float* __restrict__ pair,
                                               const float* __restrict__ Wb) {
    __shared__ float4 sp4[64 * 32];        // 32KB, rotated layout
    __shared__ float  swb[12 * 132];       // padded stride 132 (bank-spread)
    const int i  = blockIdx.y;
    const int j0 = blockIdx.x * 64;
    const int t  = threadIdx.x;

    for (int x = t; x < NH * CP; x += 256) swb[(x >> 7) * 132 + (x & 127)] = Wb[x];
    const float4* gp = (const float4*)(pair + ((size_t)i * S + j0) * CP);
#pragma unroll
    for (int r = 0; r < 8; r++) {
        int idx = t + 256 * r;
        int j = idx >> 5, q = idx & 31;
        sp4[j * 32 + ((q + j) & 31)] = gp[j * 32 + q];
    }
    __syncthreads();

    const int lane = t & 31, w = t >> 5;
    const int jq = lane >> 2, hq = lane & 3;
    const int j  = w * 8 + jq;
    const int h0 = hq * 3;
    u64 acc[3][2] = {};

#pragma unroll
    for (int q = 0; q < 32; q++) {
        float4 pA = sp4[j * 32 + ((q + j) & 31)];
        u64 pxy = pk(pA.x, pA.y), pzw = pk(pA.z, pA.w);
#pragma unroll
        for (int r = 0; r < 3; r++) {
            float4 wv = *(const float4*)&swb[(h0 + r) * 132 + q * 4];
            fma2(acc[r][0], pxy, pk(wv.x, wv.y));
            fma2(acc[r][1], pzw, pk(wv.z, wv.w));
        }
    }
#pragma unroll
    for (int r = 0; r < 3; r++) {
        float2 a = upk(acc[r][0]), b = upk(acc[r][1]);
        g_wpair[((size_t)(h0 + r) * S + i) * S + j0 + j] = a.x + a.y + b.x + b.y;
    }
}

// ---------------- K3: logits as 29-dim augmented dot + softmax -------------
// logit(i,j) = Q'_i . K'_j + wpair(i,j)  (row-constant cf|lqp|^2 dropped)
__global__ void __launch_bounds__(512, 2) k_soft() {
    extern __shared__ float sm[];
    float* ks = sm;                        // [29][768]
    float* sq = sm + KD * S;               // [16 rows][32]
    const int h  = blockIdx.y;
    const int i0 = blockIdx.x * 16;
    const int t  = threadIdx.x;

    for (int x = t; x < KD * S; x += 512) ks[x] = g_kp2[(size_t)h * KD * S + x];
    sq[t] = g_qp2[(size_t)(h * S + i0 + (t >> 5)) * 32 + (t & 31)];
    __syncthreads();

    const int w = t >> 5, lane = t & 31;
    const int i = i0 + w;
    const float* wp = g_wpair + ((size_t)h * S + i) * S + lane * 4;

    u64 lo[6], hi[6];
#pragma unroll
    for (int b = 0; b < 6; b++) {
        float4 v = *(const float4*)&wp[b * 128];
        lo[b] = pk(v.x, v.y); hi[b] = pk(v.z, v.w);
    }
#pragma unroll
    for (int e = 0; e < KD; e++) {
        float qe = sq[w * 32 + e];
        u64 q2 = pk(qe, qe);
        const float* kr = ks + e * S + lane * 4;
#pragma unroll
        for (int b = 0; b < 6; b++) {
            float4 kk = *(const float4*)&kr[b * 128];
            fma2(lo[b], q2, pk(kk.x, kk.y));
            fma2(hi[b], q2, pk(kk.z, kk.w));
        }
    }

    float4 l4[6];
    float m = -1e30f;
#pragma unroll
    for (int b = 0; b < 6; b++) {
        float2 a = upk(lo[b]), c = upk(hi[b]);
        l4[b] = make_float4(a.x, a.y, c.x, c.y);
        m = fmaxf(m, fmaxf(fmaxf(a.x, a.y), fmaxf(c.x, c.y)));
    }
#pragma unroll
    for (int o = 16; o > 0; o >>= 1) m = fmaxf(m, __shfl_xor_sync(0xffffffffu, m, o));
    float sum = 0.0f;
#pragma unroll
    for (int b = 0; b < 6; b++) {
        l4[b].x = __expf(l4[b].x - m); l4[b].y = __expf(l4[b].y - m);
        l4[b].z = __expf(l4[b].z - m); l4[b].w = __expf(l4[b].w - m);
        sum += (l4[b].x + l4[b].y) + (l4[b].z + l4[b].w);
    }
#pragma unroll
    for (int o = 16; o > 0; o >>= 1) sum += __shfl_xor_sync(0xffffffffu, sum, o);
    float inv = 1.0f / sum;
    float* ap = g_a + ((size_t)h * S + i) * S + lane * 4;
#pragma unroll
    for (int b = 0; b < 6; b++) {
        float4 o = make_float4(l4[b].x * inv, l4[b].y * inv, l4[b].z * inv, l4[b].w * inv);
        *(float4*)&ap[b * 128] = o;
    }
}

// ---------------- K4: column sums of a (two-stage) -------------------------
__global__ void k_asum1() {                 // grid (6, 12, 12), 128 thr
    const int j = blockIdx.x * 128 + threadIdx.x;
    const int h = blockIdx.y, z = blockIdx.z;
    const float* ap = g_a + (size_t)h * S * S + (size_t)z * 64 * S + j;
    float a0 = 0, a1 = 0, a2 = 0, a3 = 0;
#pragma unroll
    for (int r = 0; r < 16; r++) {
        a0 += ap[(size_t)(4 * r + 0) * S];
        a1 += ap[(size_t)(4 * r + 1) * S];
        a2 += ap[(size_t)(4 * r + 2) * S];
        a3 += ap[(size_t)(4 * r + 3) * S];
    }
    g_asp[((size_t)z * S + j) * NH + h] = (a0 + a1) + (a2 + a3);
}
__global__ void k_asum2() {                 // grid 36, 256 thr
    const int x = blockIdx.x * 256 + threadIdx.x;
    float s = 0.0f;
#pragma unroll
    for (int z = 0; z < 12; z++) s += g_asp[(size_t)z * S * NH + x];
    g_asumT[x] = s;
}

// ---------------- K5: o_combined = a @ U (per head) ------------------------
// grid (48 i-tiles, 12 h), 128 thr: thread = (i in 16, 6-channel group of 8).
__global__ void __launch_bounds__(128) k_av() {
    __shared__ float sa[16 * 133];
    __shared__ float su[128 * UC];
    const int h  = blockIdx.y;
    const int i0 = blockIdx.x * 16;
    const int t  = threadIdx.x;
    const int i  = t & 15, c0 = (t >> 4) * 6;
    u64 acc[3] = {};

    for (int jt = 0; jt < S; jt += 128) {
#pragma unroll
        for (int r = 0; r < 16; r++) {
            int idx = t + 128 * r;
            int ii = idx >> 7, j = idx & 127;
            sa[ii * 133 + j] = g_a[((size_t)h * S + i0 + ii) * S + jt + j];
        }
#pragma unroll
        for (int r = 0; r < 48; r++)
            su[t + 128 * r] = g_U[((size_t)h * S + jt) * UC + t + 128 * r];
        __syncthreads();
#pragma unroll 4
        for (int j = 0; j < 128; j++) {
            float av = sa[i * 133 + j];
            u64 a2 = pk(av, av);
            float2 u0 = *(const float2*)&su[j * UC + c0];
            float2 u1 = *(const float2*)&su[j * UC + c0 + 2];
            float2 u2 = *(const float2*)&su[j * UC + c0 + 4];
            fma2(acc[0], a2, pk(u0.x, u0.y));
            fma2(acc[1], a2, pk(u1.x, u1.y));
            fma2(acc[2], a2, pk(u2.x, u2.y));
        }
        __syncthreads();
    }
    float* op = g_oc + ((size_t)h * S + i0 + i) * UC + c0;
#pragma unroll
    for (int r = 0; r < 3; r++) {
        float2 v = upk(acc[r]);
        op[2 * r] = v.x; op[2 * r + 1] = v.y;
    }
}

// ---------------- K6: inverse frame + scatter into feature buffer ----------
__global__ void k_scatter(const float* __restrict__ rot, const float* __restrict__ trans) {
    int idx = blockIdx.x * blockDim.x + threadIdx.x;
    if (idx >= NH * S) return;
    int h = idx / S, s = idx % S;
    const float* oc = g_oc + (size_t)(h * S + s) * UC;
    float* f = g_feat + (size_t)s * FEAT;
#pragma unroll
    for (int e = 0; e < EMB; e++) f[h * EMB + e] = oc[e];

    float R[3][3], tv[3];
#pragma unroll
    for (int a = 0; a < 3; a++) {
        tv[a] = trans[s * 3 + a];
#pragma unroll
        for (int b = 0; b < 3; b++) R[a][b] = rot[s * 9 + a * 3 + b];
    }
#pragma unroll
    for (int p = 0; p < 8; p++) {
        float x0 = oc[16 + p * 3 + 0] - tv[0];
        float x1 = oc[16 + p * 3 + 1] - tv[1];
        float x2 = oc[16 + p * 3 + 2] - tv[2];
        float og[3];
#pragma unroll
        for (int a = 0; a < 3; a++) og[a] = R[0][a] * x0 + R[1][a] * x1 + R[2][a] * x2;
#pragma unroll
        for (int a = 0; a < 3; a++) f[1728 + p * 36 + h * 3 + a] = og[a];
        f[2016 + p * 12 + h] = sqrtf(og[0] * og[0] + og[1] * og[1] + og[2] * og[2]);
    }
}

// ---------------- K7: o_pair[i,h,c] = sum_k a_sum[k,h]*pair[i,k,c] ----------
__global__ void __launch_bounds__(128) k_opair(const float* __restrict__ pair) {
    __shared__ float sas[S * NH];
    const int i = blockIdx.x, t = threadIdx.x;
    for (int x = t; x < S * NH; x += 128) sas[x] = g_asumT[x];
    __syncthreads();

    u64 acc[6] = {};
    const float* pp = pair + (size_t)i * S * CP + t;
#pragma unroll 8
    for (int k = 0; k < S; k++) {
        float p = __ldg(pp + (size_t)k * CP);
        u64 p2 = pk(p, p);
        float4 a0 = *(const float4*)&sas[k * 12];
        float4 a1 = *(const float4*)&sas[k * 12 + 4];
        float4 a2 = *(const float4*)&sas[k * 12 + 8];
        fma2(acc[0], p2, pk(a0.x, a0.y));
        fma2(acc[1], p2, pk(a0.z, a0.w));
        fma2(acc[2], p2, pk(a1.x, a1.y));
        fma2(acc[3], p2, pk(a1.z, a1.w));
        fma2(acc[4], p2, pk(a2.x, a2.y));
        fma2(acc[5], p2, pk(a2.z, a2.w));
    }
    float* f = g_feat + (size_t)i * FEAT + 192 + t;
#pragma unroll
    for (int r = 0; r < 6; r++) {
        float2 v = upk(acc[r]);
        f[(2 * r) * CP]     = v.x;
        f[(2 * r + 1) * CP] = v.y;
    }
}

// ---------------- K8: out = feat @ Wo^T + bo --------------------------------
__global__ void k_out(const float* __restrict__ Wo, const float* __restrict__ bo,
                      float* __restrict__ out) {
    __shared__ float As[32 * 36];
    __shared__ float Bs[32 * 68];
    const int m0 = blockIdx.y * 32, n0 = blockIdx.x * 64;
    const int t  = threadIdx.x;
    const int i0 = (t & 15) * 2, j0 = (t >> 4) * 4;
    u64 acc[2][2] = {};

    for (int kt = 0; kt < FEAT; kt += 32) {
#pragma unroll
        for (int r = 0; r < 4; r++) {
            int idx = t + 256 * r;
            int i = idx >> 5, k = idx & 31;
            As[k * 36 + i] = g_feat[(size_t)(m0 + i) * FEAT + kt + k];
        }
#pragma unroll
        for (int r = 0; r < 8; r++) {
            int idx = t + 256 * r;
            int j = idx >> 5, k = idx & 31;
            Bs[k * 68 + j] = Wo[(size_t)(n0 + j) * FEAT + kt + k];
        }
        __syncthreads();
#pragma unroll
        for (int k = 0; k < 32; k++) {
            float2 a2 = *(const float2*)&As[k * 36 + i0];
            float4 b4 = *(const float4*)&Bs[k * 68 + j0];
            u64 bxy = pk(b4.x, b4.y), bzw = pk(b4.z, b4.w);
            u64 ax = pk(a2.x, a2.x), ay = pk(a2.y, a2.y);
            fma2(acc[0][0], ax, bxy); fma2(acc[0][1], ax, bzw);
            fma2(acc[1][0], ay, bxy); fma2(acc[1][1], ay, bzw);
        }
        __syncthreads();
    }
#pragma unroll
    for (int ii = 0; ii < 2; ii++) {
        float2 lo = upk(acc[ii][0]), hi = upk(acc[ii][1]);
        float* o = &out[(m0 + i0 + ii) * CS + n0 + j0];
        o[0] = lo.x + bo[n0 + j0 + 0];
        o[1] = lo.y + bo[n0 + j0 + 1];
        o[2] = hi.x + bo[n0 + j0 + 2];
        o[3] = hi.y + bo[n0 + j0 + 3];
    }
}

// ---------------------------------------------------------------------------
extern "C" void kernel_launch(void* const* d_in, const int* in_sizes, int n_in,
                              void* d_out, int out_size) {
    const float* single = (const float*)d_in[0];
    const float* pair   = (const float*)d_in[1];
    const float* rot    = (const float*)d_in[2];
    const float* trans  = (const float*)d_in[3];
    const float* Wq     = (const float*)d_in[4];
    const float* Wk     = (const float*)d_in[5];
    const float* Wv     = (const float*)d_in[6];
    const float* Wqp    = (const float*)d_in[7];
    const float* Wkp    = (const float*)d_in[8];
    const float* Wvp    = (const float*)d_in[9];
    const float* Wb     = (const float*)d_in[10];
    const float* Wo     = (const float*)d_in[11];
    const float* bo     = (const float*)d_in[12];
    const float* gamma  = (const float*)d_in[13];
    float* out = (float*)d_out;

    const int SMEM_SOFT = KD * S * 4 + 16 * 32 * 4;   // 91136 B -> 2 blocks/SM
    cudaFuncSetAttribute(k_soft, cudaFuncAttributeMaxDynamicSharedMemorySize, SMEM_SOFT);

    k_proj   <<<dim3(NPROJ / 64, S / 64), 256>>>(single, Wq, Wk, Wv, Wqp, Wkp, Wvp);
    k_frames <<<(NH * S + 255) / 256, 256>>>(rot, trans, gamma);
    k_wpair  <<<dim3(12, S), 256>>>(pair, Wb);
    k_soft   <<<dim3(S / 16, NH), 512, SMEM_SOFT>>>();
    k_asum1  <<<dim3(6, NH, 12), 128>>>();
    k_asum2  <<<36, 256>>>();
    k_av     <<<dim3(S / 16, NH), 128>>>();
    k_scatter<<<(NH * S + 255) / 256, 256>>>(rot, trans);
    k_opair  <<<S, 128>>>(pair);
    k_out    <<<dim3(CS / 64, S / 32), 256>>>(Wo, bo, out);
}

// round 5
// speedup vs baseline: 1.1229x; 1.0076x over previous
#include <cuda_runtime.h>
#include <math.h>

#define S     768
#define CS    384
#define CP    128
#define EMB   16
#define NH    12
#define NPROJ 1152          // 3*H*E + 2*H*PQ*3 + H*PV*3
#define FEAT  2112          // H*(E + CP + PV*3 + PV)
#define UC    48            // padded combined [v(16) | lvp(24) | zero-pad(8)]
#define KD    29            // augmented K' dims: k(16) + lkp(12) + cf*|lkp|^2(1)
#define RB    24            // k_soft rows per block

typedef unsigned long long u64;

// ---- packed fp32x2 FMA (FFMA2 — PTX-only on sm_103a) --------------------
__device__ __forceinline__ u64 pk(float x, float y) {
    u64 r; asm("mov.b64 %0, {%1,%2};" : "=l"(r) : "f"(x), "f"(y)); return r;
}
__device__ __forceinline__ float2 upk(u64 v) {
    float2 r; asm("mov.b64 {%0,%1}, %2;" : "=f"(r.x), "=f"(r.y) : "l"(v)); return r;
}
__device__ __forceinline__ void fma2(u64& d, u64 a, u64 b) {
    asm("fma.rn.f32x2 %0, %1, %2, %0;" : "+l"(d) : "l"(a), "l"(b));
}

// ---------------- scratch (device globals) --------------------------------
__device__ float g_P[S * NPROJ];
__device__ float g_qp2[NH * S * 32];      // Q' [h][s][32]
__device__ float g_kp2[NH * KD * S];      // K' [h][e'][s]
__device__ float g_U[NH * S * UC];        // [h][s][48]: v | lvp | 0
__device__ float g_wpair[NH * S * S];
__device__ float g_a[NH * S * S];
__device__ float g_asp[12 * S * NH];
__device__ float g_asumT[S * NH];
__device__ float g_oc[NH * S * UC];
__device__ float g_feat[S * FEAT];
__device__ float g_out2[2 * S * CS];

// ---------------- K1: packed projection GEMM P = single @ Wall^T ----------
// 32(m) x 64(n) tiles -> 432 blocks
__global__ void k_proj(const float* __restrict__ single,
                       const float* __restrict__ Wq, const float* __restrict__ Wk,
                       const float* __restrict__ Wv, const float* __restrict__ Wqp,
                       const float* __restrict__ Wkp, const float* __restrict__ Wvp) {
    __shared__ float As[32 * 36];
    __shared__ float Bs[32 * 68];
    const int n0 = blockIdx.x * 64, m0 = blockIdx.y * 32;
    const int t  = threadIdx.x;
    const int i0 = (t & 15) * 2, j0 = (t >> 4) * 4;
    u64 acc[2][2] = {};

    for (int kt = 0; kt < CS; kt += 32) {
#pragma unroll
        for (int r = 0; r < 4; r++) {
            int idx = t + 256 * r;
            int i = idx >> 5, k = idx & 31;
            As[k * 36 + i] = single[(m0 + i) * CS + kt + k];
        }
#pragma unroll
        for (int r = 0; r < 8; r++) {
            int idx = t + 256 * r;
            int j = idx >> 5, k = idx & 31;
            int n = n0 + j;
            const float* row;
            if (n < 192)      row = Wq  + n * CS;
            else if (n < 384) row = Wk  + (n - 192) * CS;
            else if (n < 576) row = Wv  + (n - 384) * CS;
            else if (n < 720) row = Wqp + (n - 576) * CS;
            else if (n < 864) row = Wkp + (n - 720) * CS;
            else              row = Wvp + (n - 864) * CS;
            Bs[k * 68 + j] = row[kt + k];
        }
        __syncthreads();
#pragma unroll
        for (int k = 0; k < 32; k++) {
            float2 a2 = *(const float2*)&As[k * 36 + i0];
            float4 b4 = *(const float4*)&Bs[k * 68 + j0];
            u64 bxy = pk(b4.x, b4.y), bzw = pk(b4.z, b4.w);
            u64 ax = pk(a2.x, a2.x), ay = pk(a2.y, a2.y);
            fma2(acc[0][0], ax, bxy); fma2(acc[0][1], ax, bzw);
            fma2(acc[1][0], ay, bxy); fma2(acc[1][1], ay, bzw);
        }
        __syncthreads();
    }
#pragma unroll
    for (int ii = 0; ii < 2; ii++) {
        float2 lo = upk(acc[ii][0]), hi = upk(acc[ii][1]);
        float* o = &g_P[(m0 + i0 + ii) * NPROJ + n0 + j0];
        o[0] = lo.x; o[1] = lo.y; o[2] = hi.x; o[3] = hi.y;
    }
}

// ---------------- K1b: frame apply + augmented Q'/K' build ----------------
__global__ void k_frames(const float* __restrict__ rot, const float* __restrict__ trans,
                         const float* __restrict__ gamma) {
    int idx = blockIdx.x * blockDim.x + threadIdx.x;
    if (idx >= NH * S) return;
    int h = idx / S, s = idx % S;

    float g  = gamma[h];
    float sp = (g > 20.f) ? g : log1pf(expf(g));
    float cf = -0.11785113f * sp;

    float R[3][3], tv[3];
#pragma unroll
    for (int a = 0; a < 3; a++) {
        tv[a] = trans[s * 3 + a];
#pragma unroll
        for (int b = 0; b < 3; b++) R[a][b] = rot[s * 9 + a * 3 + b];
    }
    const float* Ps = g_P + (size_t)s * NPROJ;
    float* qp2 = g_qp2 + (size_t)(h * S + s) * 32;

#pragma unroll
    for (int e = 0; e < EMB; e++) {
        qp2[e] = 0.25f * Ps[h * EMB + e];
        g_kp2[(h * KD + e) * S + s]        = Ps[192 + h * EMB + e];
        g_U[(size_t)(h * S + s) * UC + e]  = Ps[384 + h * EMB + e];
    }
    float m2cf = -2.0f * cf;
#pragma unroll
    for (int p = 0; p < 4; p++) {
        float x0 = Ps[576 + h * 12 + p * 3 + 0];
        float x1 = Ps[576 + h * 12 + p * 3 + 1];
        float x2 = Ps[576 + h * 12 + p * 3 + 2];
#pragma unroll
        for (int a = 0; a < 3; a++) {
            float l = R[a][0] * x0 + R[a][1] * x1 + R[a][2] * x2 + tv[a];
            qp2[16 + p * 3 + a] = m2cf * l;
        }
    }
    qp2[28] = 1.0f; qp2[29] = 0.0f; qp2[30] = 0.0f; qp2[31] = 0.0f;

    float nk = 0.0f;
#pragma unroll
    for (int p = 0; p < 4; p++) {
        float x0 = Ps[720 + h * 12 + p * 3 + 0];
        float x1 = Ps[720 + h * 12 + p * 3 + 1];
        float x2 = Ps[720 + h * 12 + p * 3 + 2];
#pragma unroll
        for (int a = 0; a < 3; a++) {
            float l = R[a][0] * x0 + R[a][1] * x1 + R[a][2] * x2 + tv[a];
            g_kp2[(h * KD + 16 + p * 3 + a) * S + s] = l;
            nk += l * l;
        }
    }
    g_kp2[(h * KD + 28) * S + s] = cf * nk;

#pragma unroll
    for (int p = 0; p < 8; p++) {
        float x0 = Ps[864 + h * 24 + p * 3 + 0];
        float x1 = Ps[864 + h * 24 + p * 3 + 1];
        float x2 = Ps[864 + h * 24 + p * 3 + 2];
#pragma unroll
        for (int a = 0; a < 3; a++)
            g_U[(size_t)(h * S + s) * UC + 16 + p * 3 + a] =
                R[a][0] * x0 + R[a][1] * x1 + R[a][2] * x2 + tv[a];
    }
#pragma unroll
    for (int c = 40; c < UC; c++) g_U[(size_t)(h * S + s) * UC + c] = 0.0f;
}

// ---------------- K2: w_pair[h,i,j] = sum_c Wb[h,c]*pair[i,j,c] ------------
__global__ void __launch_bounds__(256) k_wpair(const float* __restrict__ pair,
                                               const float* __restrict__ Wb) {
    __shared__ float4 sp4[64 * 32];
    __shared__ float  swb[12 * 132];
    const int i  = blockIdx.y;
    const int j0 = blockIdx.x * 64;
    const int t  = threadIdx.x;

    for (int x = t; x < NH * CP; x += 256) swb[(x >> 7) * 132 + (x & 127)] = Wb[x];
    const float4* gp = (const float4*)(pair + ((size_t)i * S + j0) * CP);
#pragma unroll
    for (int r = 0; r < 8; r++) {
        int idx = t + 256 * r;
        int j = idx >> 5, q = idx & 31;
        sp4[j * 32 + ((q + j) & 31)] = gp[j * 32 + q];
    }
    __syncthreads();

    const int lane = t & 31, w = t >> 5;
    const int jq = lane >> 2, hq = lane & 3;
    const int j  = w * 8 + jq;
    const int h0 = hq * 3;
    u64 acc[3][2] = {};

#pragma unroll
    for (int q = 0; q < 32; q++) {
        float4 pA = sp4[j * 32 + ((q + j) & 31)];
        u64 pxy = pk(pA.x, pA.y), pzw = pk(pA.z, pA.w);
#pragma unroll
        for (int r = 0; r < 3; r++) {
            float4 wv = *(const float4*)&swb[(h0 + r) * 132 + q * 4];
            fma2(acc[r][0], pxy, pk(wv.x, wv.y));
            fma2(acc[r][1], pzw, pk(wv.z, wv.w));
        }
    }
#pragma unroll
    for (int r = 0; r < 3; r++) {
        float2 a = upk(acc[r][0]), b = upk(acc[r][1]);
        g_wpair[((size_t)(h0 + r) * S + i) * S + j0 + j] = a.x + a.y + b.x + b.y;
    }
}

// ---------------- K3: logits + softmax, 2 rows per warp --------------------
__global__ void __launch_bounds__(384, 2) k_soft() {
    extern __shared__ float sm[];
    float* ks  = sm;                          // [29][768]
    u64*   squ = (u64*)(sm + KD * S);         // [24][32] duplicated-pack
    const int h  = blockIdx.y;
    const int i0 = blockIdx.x * RB;
    const int t  = threadIdx.x;

    for (int x = t; x < KD * S; x += 384) ks[x] = g_kp2[(size_t)h * KD * S + x];
    for (int x = t; x < RB * 32; x += 384) {
        float v = g_qp2[(size_t)(h * S + i0 + (x >> 5)) * 32 + (x & 31)];
        squ[x] = pk(v, v);
    }
    __syncthreads();

    const int w = t >> 5, lane = t & 31;
    const int r0 = i0 + w * 2;
    const float* wp0 = g_wpair + ((size_t)h * S + r0) * S + lane * 4;

    u64 A0[6], B0[6], A1[6], B1[6];
#pragma unroll
    for (int b = 0; b < 6; b++) {
        float4 v0 = *(const float4*)&wp0[b * 128];
        float4 v1 = *(const float4*)&wp0[S + b * 128];
        A0[b] = pk(v0.x, v0.y); B0[b] = pk(v0.z, v0.w);
        A1[b] = pk(v1.x, v1.y); B1[b] = pk(v1.z, v1.w);
    }
#pragma unroll
    for (int e = 0; e < KD; e++) {
        u64 q0 = squ[(w * 2) * 32 + e];
        u64 q1 = squ[(w * 2 + 1) * 32 + e];
        const float* kr = ks + e * S + lane * 4;
#pragma unroll
        for (int b = 0; b < 6; b++) {
            float4 kk = *(const float4*)&kr[b * 128];
            u64 kxy = pk(kk.x, kk.y), kzw = pk(kk.z, kk.w);
            fma2(A0[b], q0, kxy); fma2(B0[b], q0, kzw);
            fma2(A1[b], q1, kxy); fma2(B1[b], q1, kzw);
        }
    }

    // ---- softmax row 0 ----
    {
        float4 l[6]; float m = -1e30f;
#pragma unroll
        for (int b = 0; b < 6; b++) {
            float2 x = upk(A0[b]), y = upk(B0[b]);
            l[b] = make_float4(x.x, x.y, y.x, y.y);
            m = fmaxf(m, fmaxf(fmaxf(x.x, x.y), fmaxf(y.x, y.y)));
        }
#pragma unroll
        for (int o = 16; o > 0; o >>= 1) m = fmaxf(m, __shfl_xor_sync(0xffffffffu, m, o));
        float sum = 0.0f;
#pragma unroll
        for (int b = 0; b < 6; b++) {
            l[b].x = __expf(l[b].x - m); l[b].y = __expf(l[b].y - m);
            l[b].z = __expf(l[b].z - m); l[b].w = __expf(l[b].w - m);
            sum += (l[b].x + l[b].y) + (l[b].z + l[b].w);
        }
#pragma unroll
        for (int o = 16; o > 0; o >>= 1) sum += __shfl_xor_sync(0xffffffffu, sum, o);
        float inv = 1.0f / sum;
        float* ap = g_a + ((size_t)h * S + r0) * S + lane * 4;
#pragma unroll
        for (int b = 0; b < 6; b++)
            *(float4*)&ap[b * 128] =
                make_float4(l[b].x * inv, l[b].y * inv, l[b].z * inv, l[b].w * inv);
    }
    // ---- softmax row 1 ----
    {
        float4 l[6]; float m = -1e30f;
#pragma unroll
        for (int b = 0; b < 6; b++) {
            float2 x = upk(A1[b]), y = upk(B1[b]);
            l[b] = make_float4(x.x, x.y, y.x, y.y);
            m = fmaxf(m, fmaxf(fmaxf(x.x, x.y), fmaxf(y.x, y.y)));
        }
#pragma unroll
        for (int o = 16; o > 0; o >>= 1) m = fmaxf(m, __shfl_xor_sync(0xffffffffu, m, o));
        float sum = 0.0f;
#pragma unroll
        for (int b = 0; b < 6; b++) {
            l[b].x = __expf(l[b].x - m); l[b].y = __expf(l[b].y - m);
            l[b].z = __expf(l[b].z - m); l[b].w = __expf(l[b].w - m);
            sum += (l[b].x + l[b].y) + (l[b].z + l[b].w);
        }
#pragma unroll
        for (int o = 16; o > 0; o >>= 1) sum += __shfl_xor_sync(0xffffffffu, sum, o);
        float inv = 1.0f / sum;
        float* ap = g_a + ((size_t)h * S + r0 + 1) * S + lane * 4;
#pragma unroll
        for (int b = 0; b < 6; b++)
            *(float4*)&ap[b * 128] =
                make_float4(l[b].x * inv, l[b].y * inv, l[b].z * inv, l[b].w * inv);
    }
}

// ---------------- K4: column sums of a (two-stage, float4) -----------------
__global__ void k_asum1() {                 // grid (3, 12, 12), 64 thr
    const int j4 = blockIdx.x * 64 + threadIdx.x;
    const int h = blockIdx.y, z = blockIdx.z;
    const float4* ap = (const float4*)(g_a + (size_t)h * S * S + (size_t)z * 64 * S) + j4;
    float4 s = make_float4(0.f, 0.f, 0.f, 0.f);
#pragma unroll 8
    for (int r = 0; r < 64; r++) {
        float4 v = ap[(size_t)r * (S / 4)];
        s.x += v.x; s.y += v.y; s.z += v.z; s.w += v.w;
    }
    int j = j4 * 4;
    g_asp[((size_t)z * S + j + 0) * NH + h] = s.x;
    g_asp[((size_t)z * S + j + 1) * NH + h] = s.y;
    g_asp[((size_t)z * S + j + 2) * NH + h] = s.z;
    g_asp[((size_t)z * S + j + 3) * NH + h] = s.w;
}
__global__ void k_asum2() {                 // grid 36, 256 thr
    const int x = blockIdx.x * 256 + threadIdx.x;
    float s = 0.0f;
#pragma unroll
    for (int z = 0; z < 12; z++) s += g_asp[(size_t)z * S * NH + x];
    g_asumT[x] = s;
}

// ---------------- K5: o_combined = a @ U (per head), 2 rows/thread ---------
__global__ void __launch_bounds__(128) k_av() {
    __shared__ float sa[32 * 132];
    __shared__ float su[128 * UC];
    const int h  = blockIdx.y;
    const int i0 = blockIdx.x * 32;
    const int t  = threadIdx.x;
    const int rr = (t & 15) * 2, c0 = (t >> 4) * 6;
    u64 acc0[3] = {}, acc1[3] = {};

    for (int jt = 0; jt < S; jt += 128) {
#pragma unroll
        for (int r = 0; r < 32; r++) {
            int idx = t + 128 * r;
            int ii = idx >> 7, j = idx & 127;
            sa[ii * 132 + j] = g_a[((size_t)h * S + i0 + ii) * S + jt + j];
        }
#pragma unroll
        for (int r = 0; r < 48; r++)
            su[t + 128 * r] = g_U[((size_t)h * S + jt) * UC + t + 128 * r];
        __syncthreads();
#pragma unroll 4
        for (int j = 0; j < 128; j++) {
            float a0 = sa[rr * 132 + j], a1 = sa[(rr + 1) * 132 + j];
            u64 p0 = pk(a0, a0), p1 = pk(a1, a1);
            const u64* uu = (const u64*)&su[j * UC + c0];
            u64 u0 = uu[0], u1 = uu[1], u2 = uu[2];
            fma2(acc0[0], p0, u0); fma2(acc0[1], p0, u1); fma2(acc0[2], p0, u2);
            fma2(acc1[0], p1, u0); fma2(acc1[1], p1, u1); fma2(acc1[2], p1, u2);
        }
        __syncthreads();
    }
    float* op = g_oc + ((size_t)h * S + i0 + rr) * UC + c0;
#pragma unroll
    for (int r = 0; r < 3; r++) {
        float2 v0 = upk(acc0[r]), v1 = upk(acc1[r]);
        op[2 * r] = v0.x; op[2 * r + 1] = v0.y;
        op[UC + 2 * r] = v1.x; op[UC + 2 * r + 1] = v1.y;
    }
}

// ---------------- K6: inverse frame + scatter into feature buffer ----------
__global__ void k_scatter(const float* __restrict__ rot, const float* __restrict__ trans) {
    int idx = blockIdx.x * blockDim.x + threadIdx.x;
    if (idx >= NH * S) return;
    int h = idx / S, s = idx % S;
    const float* oc = g_oc + (size_t)(h * S + s) * UC;
    float* f = g_feat + (size_t)s * FEAT;
#pragma unroll
    for (int e = 0; e < EMB; e++) f[h * EMB + e] = oc[e];

    float R[3][3], tv[3];
#pragma unroll
    for (int a = 0; a < 3; a++) {
        tv[a] = trans[s * 3 + a];
#pragma unroll
        for (int b = 0; b < 3; b++) R[a][b] = rot[s * 9 + a * 3 + b];
    }
#pragma unroll
    for (int p = 0; p < 8; p++) {
        float x0 = oc[16 + p * 3 + 0] - tv[0];
        float x1 = oc[16 + p * 3 + 1] - tv[1];
        float x2 = oc[16 + p * 3 + 2] - tv[2];
        float og[3];
#pragma unroll
        for (int a = 0; a < 3; a++) og[a] = R[0][a] * x0 + R[1][a] * x1 + R[2][a] * x2;
#pragma unroll
        for (int a = 0; a < 3; a++) f[1728 + p * 36 + h * 3 + a] = og[a];
        f[2016 + p * 12 + h] = sqrtf(og[0] * og[0] + og[1] * og[1] + og[2] * og[2]);
    }
}

// ---------------- K7: o_pair — 2 rows/block, float4 loads, k-split 4 -------
__global__ void __launch_bounds__(256) k_opair(const float* __restrict__ pair) {
    __shared__ float sas[S * NH];            // 36 KB; later reused as buf
    const int t   = threadIdx.x;
    const int row = t >> 7;
    const int i   = blockIdx.x * 2 + row;
    const int lt  = t & 127;
    const int c4  = lt & 31, kk = lt >> 5;   // c4: float4 channel, kk: k-phase

    for (int x = t; x < S * NH; x += 256) sas[x] = g_asumT[x];
    __syncthreads();

    u64 acc[4][6] = {};                      // [c in float4][head-pair]
    const float4* pp = (const float4*)(pair + (size_t)i * S * CP) + c4;
#pragma unroll 2
    for (int k = kk; k < S; k += 4) {
        float4 p = __ldg(pp + (size_t)k * 32);
        const u64* au = (const u64*)&sas[k * 12];
        u64 a0 = au[0], a1 = au[1], a2 = au[2], a3 = au[3], a4 = au[4], a5 = au[5];
        u64 px = pk(p.x, p.x), py = pk(p.y, p.y), pz = pk(p.z, p.z), pw = pk(p.w, p.w);
        fma2(acc[0][0], px, a0); fma2(acc[0][1], px, a1); fma2(acc[0][2], px, a2);
        fma2(acc[0][3], px, a3); fma2(acc[0][4], px, a4); fma2(acc[0][5], px, a5);
        fma2(acc[1][0], py, a0); fma2(acc[1][1], py, a1); fma2(acc[1][2], py, a2);
        fma2(acc[1][3], py, a3); fma2(acc[1][4], py, a4); fma2(acc[1][5], py, a5);
        fma2(acc[2][0], pz, a0); fma2(acc[2][1], pz, a1); fma2(acc[2][2], pz, a2);
        fma2(acc[2][3], pz, a3); fma2(acc[2][4], pz, a4); fma2(acc[2][5], pz, a5);
        fma2(acc[3][0], pw, a0); fma2(acc[3][1], pw, a1); fma2(acc[3][2], pw, a2);
        fma2(acc[3][3], pw, a3); fma2(acc[3][4], pw, a4); fma2(acc[3][5], pw, a5);
    }
    __syncthreads();

    float* mine = sas + (size_t)(row * 32 + c4) * 48;   // [12h][4c]
    if (kk == 0) {
#pragma unroll
        for (int c = 0; c < 4; c++)
#pragma unroll
            for (int hp = 0; hp < 6; hp++) {
                float2 v = upk(acc[c][hp]);
                mine[(2 * hp) * 4 + c] = v.x;
                mine[(2 * hp + 1) * 4 + c] = v.y;
            }
    }
    __syncthreads();
#pragma unroll
    for (int g = 1; g < 4; g++) {
        if (kk == g) {
#pragma unroll
            for (int c = 0; c < 4; c++)
#pragma unroll
                for (int hp = 0; hp < 6; hp++) {
                    float2 v = upk(acc[c][hp]);
                    mine[(2 * hp) * 4 + c] += v.x;
                    mine[(2 * hp + 1) * 4 + c] += v.y;
                }
        }
        __syncthreads();
    }
    if (kk == 0) {
        float* f = g_feat + (size_t)i * FEAT + 192 + c4 * 4;
#pragma unroll
        for (int hh = 0; hh < 12; hh++)
            *(float4*)&f[hh * CP] = *(const float4*)&mine[hh * 4];
    }
}

// ---------------- K8: out partials = feat @ Wo^T (64x64, split-K=2) --------
__global__ void k_out(const float* __restrict__ Wo) {
    __shared__ float As[32 * 68];
    __shared__ float Bs[32 * 68];
    const int n0 = blockIdx.x * 64, m0 = blockIdx.y * 64, z = blockIdx.z;
    const int t  = threadIdx.x;
    const int i0 = (t & 15) * 4, j0 = (t >> 4) * 4;
    const int kbase = z * (FEAT / 2);
    u64 acc[4][2] = {};

    for (int kt = 0; kt < FEAT / 2; kt += 32) {
#pragma unroll
        for (int r = 0; r < 8; r++) {
            int idx = t + 256 * r;
            int i = idx >> 5, k = idx & 31;
            As[k * 68 + i] = g_feat[(size_t)(m0 + i) * FEAT + kbase + kt + k];
        }
#pragma unroll
        for (int r = 0; r < 8; r++) {
            int idx = t + 256 * r;
            int j = idx >> 5, k = idx & 31;
            Bs[k * 68 + j] = Wo[(size_t)(n0 + j) * FEAT + kbase + kt + k];
        }
        __syncthreads();
#pragma unroll
        for (int k = 0; k < 32; k++) {
            float4 a4 = *(const float4*)&As[k * 68 + i0];
            float4 b4 = *(const float4*)&Bs[k * 68 + j0];
            u64 bxy = pk(b4.x, b4.y), bzw = pk(b4.z, b4.w);
            float av[4] = {a4.x, a4.y, a4.z, a4.w};
#pragma unroll
            for (int ii = 0; ii < 4; ii++) {
                u64 aa = pk(av[ii], av[ii]);
                fma2(acc[ii][0], aa, bxy);
                fma2(acc[ii][1], aa, bzw);
            }
        }
        __syncthreads();
    }
#pragma unroll
    for (int ii = 0; ii < 4; ii++) {
        float2 lo = upk(acc[ii][0]), hi = upk(acc[ii][1]);
        float* o = &g_out2[(size_t)z * S * CS + (m0 + i0 + ii) * CS + n0 + j0];
        o[0] = lo.x; o[1] = lo.y; o[2] = hi.x; o[3] = hi.y;
    }
}

// ---------------- K9: combine split-K partials + bias ----------------------
__global__ void k_bias(const float* __restrict__ bo, float* __restrict__ out) {
    int x = blockIdx.x * 256 + threadIdx.x;          // float4 index
    float4 a = ((const float4*)g_out2)[x];
    float4 b = ((const float4*)g_out2)[S * CS / 4 + x];
    int n = (x * 4) % CS;
    float4 bb = *(const float4*)&bo[n];
    float4 o = make_float4(a.x + b.x + bb.x, a.y + b.y + bb.y,
                           a.z + b.z + bb.z, a.w + b.w + bb.w);
    ((float4*)out)[x] = o;
}

// ---------------------------------------------------------------------------
extern "C" void kernel_launch(void* const* d_in, const int* in_sizes, int n_in,
                              void* d_out, int out_size) {
    const float* single = (const float*)d_in[0];
    const float* pair   = (const float*)d_in[1];
    const float* rot    = (const float*)d_in[2];
    const float* trans  = (const float*)d_in[3];
    const float* Wq     = (const float*)d_in[4];
    const float* Wk     = (const float*)d_in[5];
    const float* Wv     = (const float*)d_in[6];
    const float* Wqp    = (const float*)d_in[7];
    const float* Wkp    = (const float*)d_in[8];
    const float* Wvp    = (const float*)d_in[9];
    const float* Wb     = (const float*)d_in[10];
    const float* Wo     = (const float*)d_in[11];
    const float* bo     = (const float*)d_in[12];
    const float* gamma  = (const float*)d_in[13];
    float* out = (float*)d_out;

    const int SMEM_SOFT = KD * S * 4 + RB * 32 * 8;   // 95232 B -> 2 blocks/SM
    cudaFuncSetAttribute(k_soft, cudaFuncAttributeMaxDynamicSharedMemorySize, SMEM_SOFT);

    k_proj   <<<dim3(NPROJ / 64, S / 32), 256>>>(single, Wq, Wk, Wv, Wqp, Wkp, Wvp);
    k_frames <<<(NH * S + 255) / 256, 256>>>(rot, trans, gamma);
    k_wpair  <<<dim3(12, S), 256>>>(pair, Wb);
    k_soft   <<<dim3(S / RB, NH), 384, SMEM_SOFT>>>();
    k_asum1  <<<dim3(3, NH, 12), 64>>>();
    k_asum2  <<<36, 256>>>();
    k_av     <<<dim3(S / 32, NH), 128>>>();
    k_scatter<<<(NH * S + 255) / 256, 256>>>(rot, trans);
    k_opair  <<<S / 2, 256>>>(pair);
    k_out    <<<dim3(CS / 64, S / 64, 2), 256>>>(Wo);
    k_bias   <<<(S * CS / 4) / 256, 256>>>(bo, out);
}

// round 6
// speedup vs baseline: 1.3527x; 1.2046x over previous
#include <cuda_runtime.h>
#include <math.h>

#define S     768
#define CS    384
#define CP    128
#define EMB   16
#define NH    12
#define NPROJ 1152          // 3*H*E + 2*H*PQ*3 + H*PV*3
#define FEAT  2112          // H*(E + CP + PV*3 + PV)
#define UC    48            // padded combined [v(16) | lvp(24) | zero-pad(8)]
#define KD    29            // augmented K' dims

typedef unsigned long long u64;

// ---- packed fp32x2 FMA (FFMA2 — PTX-only on sm_103a) --------------------
__device__ __forceinline__ u64 pk(float x, float y) {
    u64 r; asm("mov.b64 %0, {%1,%2};" : "=l"(r) : "f"(x), "f"(y)); return r;
}
__device__ __forceinline__ float2 upk(u64 v) {
    float2 r; asm("mov.b64 {%0,%1}, %2;" : "=f"(r.x), "=f"(r.y) : "l"(v)); return r;
}
__device__ __forceinline__ void fma2(u64& d, u64 a, u64 b) {
    asm("fma.rn.f32x2 %0, %1, %2, %0;" : "+l"(d) : "l"(a), "l"(b));
}
// ---- cp.async helpers -----------------------------------------------------
__device__ __forceinline__ unsigned sptr(const void* p) {
    return (unsigned)__cvta_generic_to_shared(p);
}
#define CP16(dst, src) asm volatile("cp.async.cg.shared.global [%0], [%1], 16;" :: "r"(dst), "l"(src))
#define CP_COMMIT()    asm volatile("cp.async.commit_group;")
#define CP_WAIT1()     asm volatile("cp.async.wait_group 1;" ::: "memory")
#define CP_WAIT0()     asm volatile("cp.async.wait_group 0;" ::: "memory")

// ---------------- scratch (device globals) --------------------------------
__device__ float g_P[S * NPROJ];
__device__ float g_qp2[NH * S * 32];
__device__ float g_kp2[NH * KD * S];
__device__ float g_U[NH * S * UC];
__device__ float g_wpair[NH * S * S];
__device__ float g_a[NH * S * S];
__device__ float g_asp[12 * S * NH];
__device__ float g_asumT[S * NH];
__device__ float g_oc[NH * S * UC];
__device__ float g_feat[S * FEAT];
__device__ float g_out2[2 * S * CS];

// ---------------- K1: packed projection GEMM ------------------------------
__global__ void k_proj(const float* __restrict__ single,
                       const float* __restrict__ Wq, const float* __restrict__ Wk,
                       const float* __restrict__ Wv, const float* __restrict__ Wqp,
                       const float* __restrict__ Wkp, const float* __restrict__ Wvp) {
    __shared__ float As[32 * 36];
    __shared__ float Bs[32 * 68];
    const int n0 = blockIdx.x * 64, m0 = blockIdx.y * 32;
    const int t  = threadIdx.x;
    const int i0 = (t & 15) * 2, j0 = (t >> 4) * 4;
    u64 acc[2][2] = {};

    for (int kt = 0; kt < CS; kt += 32) {
#pragma unroll
        for (int r = 0; r < 4; r++) {
            int idx = t + 256 * r;
            int i = idx >> 5, k = idx & 31;
            As[k * 36 + i] = single[(m0 + i) * CS + kt + k];
        }
#pragma unroll
        for (int r = 0; r < 8; r++) {
            int idx = t + 256 * r;
            int j = idx >> 5, k = idx & 31;
            int n = n0 + j;
            const float* row;
            if (n < 192)      row = Wq  + n * CS;
            else if (n < 384) row = Wk  + (n - 192) * CS;
            else if (n < 576) row = Wv  + (n - 384) * CS;
            else if (n < 720) row = Wqp + (n - 576) * CS;
            else if (n < 864) row = Wkp + (n - 720) * CS;
            else              row = Wvp + (n - 864) * CS;
            Bs[k * 68 + j] = row[kt + k];
        }
        __syncthreads();
#pragma unroll
        for (int k = 0; k < 32; k++) {
            float2 a2 = *(const float2*)&As[k * 36 + i0];
            float4 b4 = *(const float4*)&Bs[k * 68 + j0];
            u64 bxy = pk(b4.x, b4.y), bzw = pk(b4.z, b4.w);
            u64 ax = pk(a2.x, a2.x), ay = pk(a2.y, a2.y);
            fma2(acc[0][0], ax, bxy); fma2(acc[0][1], ax, bzw);
            fma2(acc[1][0], ay, bxy); fma2(acc[1][1], ay, bzw);
        }
        __syncthreads();
    }
#pragma unroll
    for (int ii = 0; ii < 2; ii++) {
        float2 lo = upk(acc[ii][0]), hi = upk(acc[ii][1]);
        float* o = &g_P[(m0 + i0 + ii) * NPROJ + n0 + j0];
        o[0] = lo.x; o[1] = lo.y; o[2] = hi.x; o[3] = hi.y;
    }
}

// ---------------- K1b: frame apply + augmented Q'/K' build ----------------
__global__ void k_frames(const float* __restrict__ rot, const float* __restrict__ trans,
                         const float* __restrict__ gamma) {
    int idx = blockIdx.x * blockDim.x + threadIdx.x;
    if (idx >= NH * S) return;
    int h = idx / S, s = idx % S;

    float g  = gamma[h];
    float sp = (g > 20.f) ? g : log1pf(expf(g));
    float cf = -0.11785113f * sp;

    float R[3][3], tv[3];
#pragma unroll
    for (int a = 0; a < 3; a++) {
        tv[a] = trans[s * 3 + a];
#pragma unroll
        for (int b = 0; b < 3; b++) R[a][b] = rot[s * 9 + a * 3 + b];
    }
    const float* Ps = g_P + (size_t)s * NPROJ;
    float* qp2 = g_qp2 + (size_t)(h * S + s) * 32;

#pragma unroll
    for (int e = 0; e < EMB; e++) {
        qp2[e] = 0.25f * Ps[h * EMB + e];
        g_kp2[(h * KD + e) * S + s]        = Ps[192 + h * EMB + e];
        g_U[(size_t)(h * S + s) * UC + e]  = Ps[384 + h * EMB + e];
    }
    float m2cf = -2.0f * cf;
#pragma unroll
    for (int p = 0; p < 4; p++) {
        float x0 = Ps[576 + h * 12 + p * 3 + 0];
        float x1 = Ps[576 + h * 12 + p * 3 + 1];
        float x2 = Ps[576 + h * 12 + p * 3 + 2];
#pragma unroll
        for (int a = 0; a < 3; a++) {
            float l = R[a][0] * x0 + R[a][1] * x1 + R[a][2] * x2 + tv[a];
            qp2[16 + p * 3 + a] = m2cf * l;
        }
    }
    qp2[28] = 1.0f; qp2[29] = 0.0f; qp2[30] = 0.0f; qp2[31] = 0.0f;

    float nk = 0.0f;
#pragma unroll
    for (int p = 0; p < 4; p++) {
        float x0 = Ps[720 + h * 12 + p * 3 + 0];
        float x1 = Ps[720 + h * 12 + p * 3 + 1];
        float x2 = Ps[720 + h * 12 + p * 3 + 2];
#pragma unroll
        for (int a = 0; a < 3; a++) {
            float l = R[a][0] * x0 + R[a][1] * x1 + R[a][2] * x2 + tv[a];
            g_kp2[(h * KD + 16 + p * 3 + a) * S + s] = l;
            nk += l * l;
        }
    }
    g_kp2[(h * KD + 28) * S + s] = cf * nk;

#pragma unroll
    for (int p = 0; p < 8; p++) {
        float x0 = Ps[864 + h * 24 + p * 3 + 0];
        float x1 = Ps[864 + h * 24 + p * 3 + 1];
        float x2 = Ps[864 + h * 24 + p * 3 + 2];
#pragma unroll
        for (int a = 0; a < 3; a++)
            g_U[(size_t)(h * S + s) * UC + 16 + p * 3 + a] =
                R[a][0] * x0 + R[a][1] * x1 + R[a][2] * x2 + tv[a];
    }
#pragma unroll
    for (int c = 40; c < UC; c++) g_U[(size_t)(h * S + s) * UC + c] = 0.0f;
}

// ---------------- K2: w_pair — cp.async pipelined, one i-row per block -----
// block 128 thr; 12 chunks of 64 j (32KB) double-buffered.
// thread = (warp w: 0..3, jq: 0..7, hq: 0..3) -> j = w*16+jq*2 (+1), h = hq*3..+2
__global__ void __launch_bounds__(128) k_wpair(const float* __restrict__ pair,
                                               const float* __restrict__ Wb) {
    extern __shared__ float sm[];
    float4* buf = (float4*)sm;                 // [2][64*32] float4 rotated
    float*  swb = sm + 2 * 64 * 32 * 4;        // [12][132]
    const u64* swbu = (const u64*)swb;
    const int i = blockIdx.x;
    const int t = threadIdx.x;

    for (int x = t; x < NH * CP; x += 128) swb[(x >> 7) * 132 + (x & 127)] = Wb[x];

    const float4* gp = (const float4*)pair + (size_t)i * S * 32;
    // prefetch chunk 0
#pragma unroll
    for (int r = 0; r < 16; r++) {
        int idx = t + 128 * r;
        int j = idx >> 5, q = idx & 31;
        CP16(sptr(&buf[j * 32 + ((q + (j >> 1)) & 31)]), gp + idx);
    }
    CP_COMMIT();

    const int lane = t & 31, w = t >> 5;
    const int jq = lane >> 2, hq = lane & 3;
    const int jA = w * 16 + jq * 2;
    const int h0 = hq * 3;

    for (int c = 0; c < 12; c++) {
        float4* cur = buf + (c & 1) * (64 * 32);
        if (c + 1 < 12) {
            float4* nxt = buf + ((c + 1) & 1) * (64 * 32);
            const float4* gsrc = gp + (c + 1) * 64 * 32;
#pragma unroll
            for (int r = 0; r < 16; r++) {
                int idx = t + 128 * r;
                int j = idx >> 5, q = idx & 31;
                CP16(sptr(&nxt[j * 32 + ((q + (j >> 1)) & 31)]), gsrc + idx);
            }
        }
        CP_COMMIT();
        CP_WAIT1();
        __syncthreads();

        u64 accA[3][2] = {}, accB[3][2] = {};
#pragma unroll
        for (int q = 0; q < 32; q++) {
            int slot = (q + (jA >> 1)) & 31;
            const u64* pA = (const u64*)&cur[jA * 32 + slot];
            const u64* pB = (const u64*)&cur[(jA + 1) * 32 + slot];
            u64 a0 = pA[0], a1 = pA[1];
            u64 b0 = pB[0], b1 = pB[1];
#pragma unroll
            for (int r = 0; r < 3; r++) {
                u64 w0 = swbu[(h0 + r) * 66 + 2 * q];
                u64 w1 = swbu[(h0 + r) * 66 + 2 * q + 1];
                fma2(accA[r][0], a0, w0); fma2(accA[r][1], a1, w1);
                fma2(accB[r][0], b0, w0); fma2(accB[r][1], b1, w1);
            }
        }
        int j0 = c * 64;
#pragma unroll
        for (int r = 0; r < 3; r++) {
            float2 xa = upk(accA[r][0]), ya = upk(accA[r][1]);
            float2 xb = upk(accB[r][0]), yb = upk(accB[r][1]);
            float* wrow = g_wpair + ((size_t)(h0 + r) * S + i) * S + j0 + jA;
            wrow[0] = xa.x + xa.y + ya.x + ya.y;
            wrow[1] = xb.x + xb.y + yb.x + yb.y;
        }
        __syncthreads();
    }
}

// ---------------- K3: logits + softmax (R4 layout: 1 row/warp, 512 thr) ----
__global__ void __launch_bounds__(512, 2) k_soft() {
    extern __shared__ float sm[];
    float* ks = sm;                        // [29][768]
    float* sq = sm + KD * S;               // [16 rows][32]
    const int h  = blockIdx.y;
    const int i0 = blockIdx.x * 16;
    const int t  = threadIdx.x;

    for (int x = t; x < KD * S; x += 512) ks[x] = g_kp2[(size_t)h * KD * S + x];
    sq[t] = g_qp2[(size_t)(h * S + i0 + (t >> 5)) * 32 + (t & 31)];
    __syncthreads();

    const int w = t >> 5, lane = t & 31;
    const int i = i0 + w;
    const float* wp = g_wpair + ((size_t)h * S + i) * S + lane * 4;

    u64 lo[6], hi[6];
#pragma unroll
    for (int b = 0; b < 6; b++) {
        float4 v = *(const float4*)&wp[b * 128];
        lo[b] = pk(v.x, v.y); hi[b] = pk(v.z, v.w);
    }
#pragma unroll
    for (int e = 0; e < KD; e++) {
        float qe = sq[w * 32 + e];
        u64 q2 = pk(qe, qe);
        const float* kr = ks + e * S + lane * 4;
#pragma unroll
        for (int b = 0; b < 6; b++) {
            float4 kk = *(const float4*)&kr[b * 128];
            fma2(lo[b], q2, pk(kk.x, kk.y));
            fma2(hi[b], q2, pk(kk.z, kk.w));
        }
    }

    float4 l4[6];
    float m = -1e30f;
#pragma unroll
    for (int b = 0; b < 6; b++) {
        float2 a = upk(lo[b]), c = upk(hi[b]);
        l4[b] = make_float4(a.x, a.y, c.x, c.y);
        m = fmaxf(m, fmaxf(fmaxf(a.x, a.y), fmaxf(c.x, c.y)));
    }
#pragma unroll
    for (int o = 16; o > 0; o >>= 1) m = fmaxf(m, __shfl_xor_sync(0xffffffffu, m, o));
    float sum = 0.0f;
#pragma unroll
    for (int b = 0; b < 6; b++) {
        l4[b].x = __expf(l4[b].x - m); l4[b].y = __expf(l4[b].y - m);
        l4[b].z = __expf(l4[b].z - m); l4[b].w = __expf(l4[b].w - m);
        sum += (l4[b].x + l4[b].y) + (l4[b].z + l4[b].w);
    }
#pragma unroll
    for (int o = 16; o > 0; o >>= 1) sum += __shfl_xor_sync(0xffffffffu, sum, o);
    float inv = 1.0f / sum;
    float* ap = g_a + ((size_t)h * S + i) * S + lane * 4;
#pragma unroll
    for (int b = 0; b < 6; b++)
        *(float4*)&ap[b * 128] =
            make_float4(l4[b].x * inv, l4[b].y * inv, l4[b].z * inv, l4[b].w * inv);
}

// ---------------- K4: column sums of a (two-stage, float4) -----------------
__global__ void k_asum1() {
    const int j4 = blockIdx.x * 64 + threadIdx.x;
    const int h = blockIdx.y, z = blockIdx.z;
    const float4* ap = (const float4*)(g_a + (size_t)h * S * S + (size_t)z * 64 * S) + j4;
    float4 s = make_float4(0.f, 0.f, 0.f, 0.f);
#pragma unroll 8
    for (int r = 0; r < 64; r++) {
        float4 v = ap[(size_t)r * (S / 4)];
        s.x += v.x; s.y += v.y; s.z += v.z; s.w += v.w;
    }
    int j = j4 * 4;
    g_asp[((size_t)z * S + j + 0) * NH + h] = s.x;
    g_asp[((size_t)z * S + j + 1) * NH + h] = s.y;
    g_asp[((size_t)z * S + j + 2) * NH + h] = s.z;
    g_asp[((size_t)z * S + j + 3) * NH + h] = s.w;
}
__global__ void k_asum2() {
    const int x = blockIdx.x * 256 + threadIdx.x;
    float s = 0.0f;
#pragma unroll
    for (int z = 0; z < 12; z++) s += g_asp[(size_t)z * S * NH + x];
    g_asumT[x] = s;
}

// ---------------- K5: o_combined = a @ U — cp.async pipelined --------------
// block 256 thr = (i: 32, cg: 8 of 6 channels). 6 chunks of 128 j.
__global__ void __launch_bounds__(256) k_av() {
    extern __shared__ float sm[];
    float* sa = sm;                            // [2][32][132]
    float* su = sm + 2 * 32 * 132;             // [2][128][48]
    const int h  = blockIdx.y;
    const int i0 = blockIdx.x * 32;
    const int t  = threadIdx.x;
    const int i  = t & 31, c0 = (t >> 5) * 6;
    u64 acc[3] = {};

    const float4* ga = (const float4*)g_a;
    const float4* gu = (const float4*)g_U + (size_t)h * S * 12;

    // prefetch chunk 0
#pragma unroll
    for (int r = 0; r < 4; r++) {
        int idx = t + 256 * r;
        int ii = idx >> 5, j4 = idx & 31;
        CP16(sptr(&((float4*)sa)[ii * 33 + j4]),
             ga + ((size_t)h * S + i0 + ii) * (S / 4) + j4);
    }
#pragma unroll
    for (int r = 0; r < 6; r++) {
        int idx = t + 256 * r;
        CP16(sptr(&((float4*)su)[idx]), gu + idx);
    }
    CP_COMMIT();

    for (int c = 0; c < 6; c++) {
        float* sac = sa + (c & 1) * 32 * 132;
        float* suc = su + (c & 1) * 128 * 48;
        if (c + 1 < 6) {
            float* san = sa + ((c + 1) & 1) * 32 * 132;
            float* sun = su + ((c + 1) & 1) * 128 * 48;
            int jt4 = (c + 1) * 32;
#pragma unroll
            for (int r = 0; r < 4; r++) {
                int idx = t + 256 * r;
                int ii = idx >> 5, j4 = idx & 31;
                CP16(sptr(&((float4*)san)[ii * 33 + j4]),
                     ga + ((size_t)h * S + i0 + ii) * (S / 4) + jt4 + j4);
            }
            const float4* gun = gu + (c + 1) * 128 * 12;
#pragma unroll
            for (int r = 0; r < 6; r++) {
                int idx = t + 256 * r;
                CP16(sptr(&((float4*)sun)[idx]), gun + idx);
            }
        }
        CP_COMMIT();
        CP_WAIT1();
        __syncthreads();

#pragma unroll 4
        for (int j = 0; j < 128; j++) {
            float av = sac[i * 132 + j];
            u64 p = pk(av, av);
            const u64* uu = (const u64*)&suc[j * UC + c0];
            fma2(acc[0], p, uu[0]); fma2(acc[1], p, uu[1]); fma2(acc[2], p, uu[2]);
        }
        __syncthreads();
    }
    float* op = g_oc + ((size_t)h * S + i0 + i) * UC + c0;
#pragma unroll
    for (int r = 0; r < 3; r++) {
        float2 v = upk(acc[r]);
        op[2 * r] = v.x; op[2 * r + 1] = v.y;
    }
}

// ---------------- K6: inverse frame + scatter into feature buffer ----------
__global__ void k_scatter(const float* __restrict__ rot, const float* __restrict__ trans) {
    int idx = blockIdx.x * blockDim.x + threadIdx.x;
    if (idx >= NH * S) return;
    int h = idx / S, s = idx % S;
    const float* oc = g_oc + (size_t)(h * S + s) * UC;
    float* f = g_feat + (size_t)s * FEAT;
#pragma unroll
    for (int e = 0; e < EMB; e++) f[h * EMB + e] = oc[e];

    float R[3][3], tv[3];
#pragma unroll
    for (int a = 0; a < 3; a++) {
        tv[a] = trans[s * 3 + a];
#pragma unroll
        for (int b = 0; b < 3; b++) R[a][b] = rot[s * 9 + a * 3 + b];
    }
#pragma unroll
    for (int p = 0; p < 8; p++) {
        float x0 = oc[16 + p * 3 + 0] - tv[0];
        float x1 = oc[16 + p * 3 + 1] - tv[1];
        float x2 = oc[16 + p * 3 + 2] - tv[2];
        float og[3];
#pragma unroll
        for (int a = 0; a < 3; a++) og[a] = R[0][a] * x0 + R[1][a] * x1 + R[2][a] * x2;
#pragma unroll
        for (int a = 0; a < 3; a++) f[1728 + p * 36 + h * 3 + a] = og[a];
        f[2016 + p * 12 + h] = sqrtf(og[0] * og[0] + og[1] * og[1] + og[2] * og[2]);
    }
}

// ---------------- K7: o_pair — cp.async pipelined, one i-row per block -----
// 256 thr = (c4: 32 float4-channels, kk: 8 k-phases). 12 chunks of 64 k.
__global__ void __launch_bounds__(256) k_opair(const float* __restrict__ pair) {
    extern __shared__ float sm[];
    float4* buf = (float4*)sm;                 // [2][64*32]
    float*  sas = sm + 2 * 64 * 32 * 4;        // [768][12]
    const int i = blockIdx.x;
    const int t = threadIdx.x;
    const int c4 = t & 31, kk = t >> 5;

    for (int x = t; x < S * NH; x += 256) sas[x] = g_asumT[x];

    const float4* gp = (const float4*)pair + (size_t)i * S * 32;
#pragma unroll
    for (int r = 0; r < 8; r++) {
        int idx = t + 256 * r;
        CP16(sptr(&buf[idx]), gp + idx);
    }
    CP_COMMIT();

    u64 acc[4][6] = {};
    for (int c = 0; c < 12; c++) {
        float4* cur = buf + (c & 1) * (64 * 32);
        if (c + 1 < 12) {
            float4* nxt = buf + ((c + 1) & 1) * (64 * 32);
            const float4* gsrc = gp + (c + 1) * 64 * 32;
#pragma unroll
            for (int r = 0; r < 8; r++) {
                int idx = t + 256 * r;
                CP16(sptr(&nxt[idx]), gsrc + idx);
            }
        }
        CP_COMMIT();
        CP_WAIT1();
        __syncthreads();

        int kbase = c * 64;
#pragma unroll 4
        for (int kl = kk; kl < 64; kl += 8) {
            float4 p = cur[kl * 32 + c4];
            const u64* au = (const u64*)&sas[(kbase + kl) * 12];
            u64 a0 = au[0], a1 = au[1], a2 = au[2], a3 = au[3], a4 = au[4], a5 = au[5];
            u64 px = pk(p.x, p.x), py = pk(p.y, p.y), pz = pk(p.z, p.z), pw = pk(p.w, p.w);
            fma2(acc[0][0], px, a0); fma2(acc[0][1], px, a1); fma2(acc[0][2], px, a2);
            fma2(acc[0][3], px, a3); fma2(acc[0][4], px, a4); fma2(acc[0][5], px, a5);
            fma2(acc[1][0], py, a0); fma2(acc[1][1], py, a1); fma2(acc[1][2], py, a2);
            fma2(acc[1][3], py, a3); fma2(acc[1][4], py, a4); fma2(acc[1][5], py, a5);
            fma2(acc[2][0], pz, a0); fma2(acc[2][1], pz, a1); fma2(acc[2][2], pz, a2);
            fma2(acc[2][3], pz, a3); fma2(acc[2][4], pz, a4); fma2(acc[2][5], pz, a5);
            fma2(acc[3][0], pw, a0); fma2(acc[3][1], pw, a1); fma2(acc[3][2], pw, a2);
            fma2(acc[3][3], pw, a3); fma2(acc[3][4], pw, a4); fma2(acc[3][5], pw, a5);
        }
        __syncthreads();
    }

    // unpack accumulators: rv[c*12 + h]
    float rv[48];
#pragma unroll
    for (int cc = 0; cc < 4; cc++)
#pragma unroll
        for (int hp = 0; hp < 6; hp++) {
            float2 v = upk(acc[cc][hp]);
            rv[cc * 12 + 2 * hp]     = v.x;
            rv[cc * 12 + 2 * hp + 1] = v.y;
        }

    // log-tree reduction over 8 k-phases using freed buf space
    float* red = sm;
#pragma unroll
    for (int step = 4; step >= 1; step >>= 1) {
        if (kk >= step && kk < 2 * step) {
            float* d = red + ((kk - step) * 32 + c4) * 48;
#pragma unroll
            for (int x = 0; x < 48; x += 4)
                *(float4*)&d[x] = make_float4(rv[x], rv[x + 1], rv[x + 2], rv[x + 3]);
        }
        __syncthreads();
        if (kk < step) {
            const float* d = red + (kk * 32 + c4) * 48;
#pragma unroll
            for (int x = 0; x < 48; x++) rv[x] += d[x];
        }
        __syncthreads();
    }
    if (kk == 0) {
        float* f = g_feat + (size_t)i * FEAT + 192 + c4 * 4;
#pragma unroll
        for (int hh = 0; hh < 12; hh++)
            *(float4*)&f[hh * CP] =
                make_float4(rv[hh], rv[12 + hh], rv[24 + hh], rv[36 + hh]);
    }
}

// ---------------- K8: out partials = feat @ Wo^T (64x64, split-K=2) --------
__global__ void k_out(const float* __restrict__ Wo) {
    __shared__ float As[32 * 68];
    __shared__ float Bs[32 * 68];
    const int n0 = blockIdx.x * 64, m0 = blockIdx.y * 64, z = blockIdx.z;
    const int t  = threadIdx.x;
    const int i0 = (t & 15) * 4, j0 = (t >> 4) * 4;
    const int kbase = z * (FEAT / 2);
    u64 acc[4][2] = {};

    for (int kt = 0; kt < FEAT / 2; kt += 32) {
#pragma unroll
        for (int r = 0; r < 8; r++) {
            int idx = t + 256 * r;
            int i = idx >> 5, k = idx & 31;
            As[k * 68 + i] = g_feat[(size_t)(m0 + i) * FEAT + kbase + kt + k];
        }
#pragma unroll
        for (int r = 0; r < 8; r++) {
            int idx = t + 256 * r;
            int j = idx >> 5, k = idx & 31;
            Bs[k * 68 + j] = Wo[(size_t)(n0 + j) * FEAT + kbase + kt + k];
        }
        __syncthreads();
#pragma unroll
        for (int k = 0; k < 32; k++) {
            float4 a4 = *(const float4*)&As[k * 68 + i0];
            float4 b4 = *(const float4*)&Bs[k * 68 + j0];
            u64 bxy = pk(b4.x, b4.y), bzw = pk(b4.z, b4.w);
            float av[4] = {a4.x, a4.y, a4.z, a4.w};
#pragma unroll
            for (int ii = 0; ii < 4; ii++) {
                u64 aa = pk(av[ii], av[ii]);
                fma2(acc[ii][0], aa, bxy);
                fma2(acc[ii][1], aa, bzw);
            }
        }
        __syncthreads();
    }
#pragma unroll
    for (int ii = 0; ii < 4; ii++) {
        float2 lo = upk(acc[ii][0]), hi = upk(acc[ii][1]);
        float* o = &g_out2[(size_t)z * S * CS + (m0 + i0 + ii) * CS + n0 + j0];
        o[0] = lo.x; o[1] = lo.y; o[2] = hi.x; o[3] = hi.y;
    }
}

// ---------------- K9: combine split-K partials + bias ----------------------
__global__ void k_bias(const float* __restrict__ bo, float* __restrict__ out) {
    int x = blockIdx.x * 256 + threadIdx.x;
    float4 a = ((const float4*)g_out2)[x];
    float4 b = ((const float4*)g_out2)[S * CS / 4 + x];
    int n = (x * 4) % CS;
    float4 bb = *(const float4*)&bo[n];
    ((float4*)out)[x] = make_float4(a.x + b.x + bb.x, a.y + b.y + bb.y,
                                    a.z + b.z + bb.z, a.w + b.w + bb.w);
}

// ---------------------------------------------------------------------------
extern "C" void kernel_launch(void* const* d_in, const int* in_sizes, int n_in,
                              void* d_out, int out_size) {
    const float* single = (const float*)d_in[0];
    const float* pair   = (const float*)d_in[1];
    const float* rot    = (const float*)d_in[2];
    const float* trans  = (const float*)d_in[3];
    const float* Wq     = (const float*)d_in[4];
    const float* Wk     = (const float*)d_in[5];
    const float* Wv     = (const float*)d_in[6];
    const float* Wqp    = (const float*)d_in[7];
    const float* Wkp    = (const float*)d_in[8];
    const float* Wvp    = (const float*)d_in[9];
    const float* Wb     = (const float*)d_in[10];
    const float* Wo     = (const float*)d_in[11];
    const float* bo     = (const float*)d_in[12];
    const float* gamma  = (const float*)d_in[13];
    float* out = (float*)d_out;

    const int SMEM_WPAIR = 2 * 64 * 32 * 16 + 12 * 132 * 4;   // 71872
    const int SMEM_SOFT  = KD * S * 4 + 16 * 32 * 4;          // 91136
    const int SMEM_AV    = 2 * 32 * 132 * 4 + 2 * 128 * 48 * 4; // 82944
    const int SMEM_OPAIR = 2 * 64 * 32 * 16 + S * NH * 4;     // 102400
    cudaFuncSetAttribute(k_wpair, cudaFuncAttributeMaxDynamicSharedMemorySize, SMEM_WPAIR);
    cudaFuncSetAttribute(k_soft,  cudaFuncAttributeMaxDynamicSharedMemorySize, SMEM_SOFT);
    cudaFuncSetAttribute(k_av,    cudaFuncAttributeMaxDynamicSharedMemorySize, SMEM_AV);
    cudaFuncSetAttribute(k_opair, cudaFuncAttributeMaxDynamicSharedMemorySize, SMEM_OPAIR);

    k_proj   <<<dim3(NPROJ / 64, S / 32), 256>>>(single, Wq, Wk, Wv, Wqp, Wkp, Wvp);
    k_frames <<<(NH * S + 255) / 256, 256>>>(rot, trans, gamma);
    k_wpair  <<<S, 128, SMEM_WPAIR>>>(pair, Wb);
    k_soft   <<<dim3(S / 16, NH), 512, SMEM_SOFT>>>();
    k_asum1  <<<dim3(3, NH, 12), 64>>>();
    k_asum2  <<<36, 256>>>();
    k_av     <<<dim3(S / 32, NH), 256, SMEM_AV>>>();
    k_scatter<<<(NH * S + 255) / 256, 256>>>(rot, trans);
    k_opair  <<<S, 256, SMEM_OPAIR>>>(pair);
    k_out    <<<dim3(CS / 64, S / 64, 2), 256>>>(Wo);
    k_bias   <<<(S * CS / 4) / 256, 256>>>(bo, out);
}